// round 9
// baseline (speedup 1.0000x reference)
#include <cuda_runtime.h>
#include <cuda_fp16.h>

typedef unsigned long long u64;
typedef unsigned int u32;
#define DI __device__ __forceinline__

#define LO_SCALE 2048.f
#define LO_INV (1.f / 2048.f)

// ---------------- static scratch ----------------
__device__ __half g_h0[16*16384*256];
__device__ __half g_l0[16*16384*256];
__device__ __half g_h1[16*16384*256];
__device__ __half g_l1[16*16384*256];
__device__ float  g_zT[16*2048*64];
__device__ __half g_qh[16*2048*64];
__device__ __half g_ql[16*2048*64];
__device__ __half g_whi[9*196608];
__device__ __half g_wlo[9*196608];
__device__ float  g_cnh[512];

// ---------------- PTX helpers ----------------
DI u32 smem_u32(const void* p) {
    u32 a;
    asm("{ .reg .u64 t; cvta.to.shared.u64 t, %1; cvt.u32.u64 %0, t; }" : "=r"(a) : "l"(p));
    return a;
}
DI void cpa16(u32 dst, const void* src, int src_sz) {
    asm volatile("cp.async.cg.shared.global [%0], [%1], 16, %2;"
                 :: "r"(dst), "l"(src), "r"(src_sz) : "memory");
}
DI void cpa_commit() { asm volatile("cp.async.commit_group;" ::: "memory"); }
DI void cpa_wait1() { asm volatile("cp.async.wait_group 1;" ::: "memory"); }
DI void cpa_wait0() { asm volatile("cp.async.wait_group 0;" ::: "memory"); }
DI void ldsm4(u32* r, u32 addr) {
    asm volatile("ldmatrix.sync.aligned.m8n8.x4.shared.b16 {%0,%1,%2,%3}, [%4];"
                 : "=r"(r[0]), "=r"(r[1]), "=r"(r[2]), "=r"(r[3]) : "r"(addr));
}
DI void mma16816(float* c, const u32* a, u32 b0, u32 b1) {
    asm volatile(
        "mma.sync.aligned.m16n8k16.row.col.f32.f16.f16.f32 "
        "{%0,%1,%2,%3}, {%4,%5,%6,%7}, {%8,%9}, {%0,%1,%2,%3};"
        : "+f"(c[0]), "+f"(c[1]), "+f"(c[2]), "+f"(c[3])
        : "r"(a[0]), "r"(a[1]), "r"(a[2]), "r"(a[3]), "r"(b0), "r"(b1));
}
DI u32 swz(u32 o) { return o ^ ((o >> 3) & 0x70); }

// ---------------- weight repack + split: w[oc][ic][k] -> [(k*nch+c)][oc][64] hi/lo ----------------
__global__ void repack_kernel(const float* __restrict__ w, __half* __restrict__ wh,
                              __half* __restrict__ wl, int OC, int IC) {
    int i = blockIdx.x * 256 + threadIdx.x;
    int n = OC * IC * 3;
    if (i >= n) return;
    int oc = i / (IC * 3);
    int r = i - oc * IC * 3;
    int ic = r / 3, k = r - ic * 3;
    int nch = IC >> 6, c = ic >> 6, j = ic & 63;
    float v = w[i];
    __half h = __float2half_rn(v);
    size_t d = ((size_t)(k * nch + c) * OC + oc) * 64 + j;
    wh[d] = h;
    wl[d] = __float2half_rn((v - __half2float(h)) * LO_SCALE);
}

__global__ void cb_prep_kernel(const float* __restrict__ cb, float* __restrict__ cnh) {
    int c = threadIdx.x;
    float s = 0.f;
    for (int k = 0; k < 64; k++) { float v = cb[c * 64 + k]; s += v * v; }
    cnh[c] = 0.5f * s;
}

// ---------------- encoder layer 1: IC=1, stride 2, relu, t-major hi/lo out ----------------
__global__ void e1_kernel(const float* __restrict__ x, const float* __restrict__ w,
                          const float* __restrict__ bias,
                          __half* __restrict__ oh, __half* __restrict__ ol) {
    __shared__ float xs[132];
    int b = blockIdx.y, tc = blockIdx.x * 64, tid = threadIdx.x;
    const float* xr = x + (size_t)b * 32768;
    for (int i = tid; i < 130; i += 256) {
        int pos = 2 * tc - 1 + i;
        xs[i] = (pos >= 0 && pos < 32768) ? xr[pos] : 0.f;
    }
    __syncthreads();
    float w0 = w[tid * 3], w1 = w[tid * 3 + 1], w2 = w[tid * 3 + 2], bv = bias[tid];
    for (int j = 0; j < 64; j++) {
        float v = fmaxf(bv + w0 * xs[2 * j] + w1 * xs[2 * j + 1] + w2 * xs[2 * j + 2], 0.f);
        __half h = __float2half_rn(v);
        size_t o = ((size_t)b * 16384 + tc + j) * 256 + tid;
        oh[o] = h;
        ol[o] = __float2half_rn((v - __half2float(h)) * LO_SCALE);
    }
}

// ---------------- generic mma.sync conv GEMM (fp16-split, scaled residuals) ----------------
// mode: 0=s1 conv, 1=s2 conv, 2=convT (pair-split), 3=convT final (fp32 ch-major out)
// grid: x = oc-half (+pair for mode>=2), y = t-tile, z = batch
// MTC: 4 -> N=128 (warp tile 64x32), 2 -> N=64 (warp tile 32x32)
template <int MTC>
__global__ void __launch_bounds__(256)
conv_mma_kernel(const __half* __restrict__ in_hi, const __half* __restrict__ in_lo,
                const __half* __restrict__ w_hi, const __half* __restrict__ w_lo,
                const float* __restrict__ bias,
                __half* __restrict__ out_hi, __half* __restrict__ out_lo,
                float* __restrict__ out_f32,
                int IC, int OC, int Tin, int Tout, int mode, int relu) {
    extern __shared__ char smraw[];
    u32 sb0 = smem_u32(smraw);
    u32 sb = (sb0 + 1023) & ~1023u;
    char* smp = smraw + (sb - sb0);

    const int tid = threadIdx.x, lane = tid & 31, wid = tid >> 5;
    const int t0 = blockIdx.y * 128;
    const int N = (MTC == 4) ? 128 : 64;
    int xb = blockIdx.x;
    int oc0, pair;
    if (mode >= 2) { oc0 = (xb & 1) * 128; pair = xb >> 1; }
    else           { oc0 = xb * 128; pair = 0; }
    const int b = blockIdx.z;
    const int nch = IC >> 6;
    const int nsub = (mode < 2) ? 3 * nch : (pair ? 2 * nch : nch);
    const size_t inb = (size_t)b * Tin * IC;

    int wm, wn, mbase;
    if (MTC == 4) { wm = wid & 1; wn = wid >> 1; mbase = wm * 64; }
    else          { wm = wid >> 1; wn = wid & 1; mbase = wm * 32; }

    float acc[MTC][4][4];   // hi*hi
    float accc[MTC][4][4];  // hi*lo + lo*hi (scaled by LO_SCALE)
#pragma unroll
    for (int mt = 0; mt < MTC; mt++)
#pragma unroll
        for (int nt = 0; nt < 4; nt++)
#pragma unroll
            for (int k = 0; k < 4; k++) { acc[mt][nt][k] = 0.f; accc[mt][nt][k] = 0.f; }

    auto geo = [&](int i, int& c, int& kap, int& del) {
        if (mode < 2) { c = i / 3; int s = i - 3 * c; kap = s; del = s - 1; }
        else if (!pair) { c = i; kap = 1; del = 0; }
        else { c = i >> 1; if (i & 1) { kap = 2; del = 1; } else { kap = 0; del = 0; } }
    };
    // stage p (p=0..2): A_hi @ p*65536, A_lo +16384, B_hi +32768, B_lo +49152
    auto load_chunk = [&](int i, int p) {
        int c, kap, del;
        geo(i, c, kap, del);
        u32 abase = sb + p * 65536;
        u32 bbase = abase + 32768;
        int r0 = tid >> 3, qd = tid & 7;
        const __half* sH = in_hi + inb + c * 64 + qd * 8;
        const __half* sL = in_lo + inb + c * 64 + qd * 8;
#pragma unroll
        for (int it = 0; it < 4; it++) {
            int r = r0 + it * 32;
            int g = (mode == 1) ? (2 * (t0 + r) + del) : (t0 + r + del);
            int ok = (g >= 0 && g < Tin) ? 16 : 0;
            int gc = ok ? g : 0;
            u32 so = swz((u32)(r * 128 + qd * 16));
            cpa16(abase + so, sH + (size_t)gc * IC, ok);
            cpa16(abase + 16384 + so, sL + (size_t)gc * IC, ok);
        }
        const __half* wH = w_hi + ((size_t)(kap * nch + c) * OC + oc0) * 64 + qd * 8;
        const __half* wL = w_lo + ((size_t)(kap * nch + c) * OC + oc0) * 64 + qd * 8;
#pragma unroll
        for (int it = 0; it < 4; it++) {
            int r = r0 + it * 32;
            if (r < N) {
                u32 so = swz((u32)(r * 128 + qd * 16));
                cpa16(bbase + so, wH + (size_t)r * 64, 16);
                cpa16(bbase + 16384 + so, wL + (size_t)r * 64, 16);
            }
        }
    };

    // 3-stage pipeline prologue: chunks 0 and 1 in flight
    load_chunk(0, 0);
    cpa_commit();
    if (nsub > 1) { load_chunk(1, 1); cpa_commit(); }

    for (int i = 0; i < nsub; i++) {
        int p = i - (i / 3) * 3;
        // wait for chunk i (pending groups allowed = chunks after i that are committed)
        if (i + 1 < nsub) cpa_wait1(); else cpa_wait0();
        __syncthreads();   // chunk i visible to all; stage (i+2)%3 fully consumed by all
        // issue next-next load AFTER the barrier -> race-free, 2-chunk latency window
        if (i + 2 < nsub) { load_chunk(i + 2, (i + 2) % 3); cpa_commit(); }

        u32 abase = sb + p * 65536;
        u32 bbase = abase + 32768;
#pragma unroll
        for (int ks = 0; ks < 4; ks++) {
            u32 bh[8], bl[8];
#pragma unroll
            for (int q = 0; q < 2; q++) {
                int brow = wn * 32 + q * 16 + ((lane >> 4) & 1) * 8 + (lane & 7);
                int bkb = ks * 32 + ((lane >> 3) & 1) * 16;
                u32 bad = bbase + swz((u32)(brow * 128 + bkb));
                ldsm4(&bh[q * 4], bad);
                ldsm4(&bl[q * 4], bad + 16384);
            }
            int arow = mbase + (lane & 15);
            int akb = ks * 32 + (lane >> 4) * 16;
            u32 ah[MTC][4], al[MTC][4];
#pragma unroll
            for (int mt = 0; mt < MTC; mt++) {
                u32 aad = abase + swz((u32)((arow + mt * 16) * 128 + akb));
                ldsm4(ah[mt], aad);
                ldsm4(al[mt], aad + 16384);
            }
            // Phase 1: hh into acc
#pragma unroll
            for (int mt = 0; mt < MTC; mt++)
#pragma unroll
                for (int nt = 0; nt < 4; nt++) {
                    int bi = (nt >> 1) * 4 + (nt & 1) * 2;
                    mma16816(acc[mt][nt], ah[mt], bh[bi], bh[bi + 1]);
                }
            // Phase 2: hi*lo into accc
#pragma unroll
            for (int mt = 0; mt < MTC; mt++)
#pragma unroll
                for (int nt = 0; nt < 4; nt++) {
                    int bi = (nt >> 1) * 4 + (nt & 1) * 2;
                    mma16816(accc[mt][nt], ah[mt], bl[bi], bl[bi + 1]);
                }
            // Phase 3: lo*hi into accc
#pragma unroll
            for (int mt = 0; mt < MTC; mt++)
#pragma unroll
                for (int nt = 0; nt < 4; nt++) {
                    int bi = (nt >> 1) * 4 + (nt & 1) * 2;
                    mma16816(accc[mt][nt], al[mt], bh[bi], bh[bi + 1]);
                }
        }
    }
    __syncthreads();

    // ---------------- epilogue ----------------
    int g = lane >> 2, tg = lane & 3;
    float* stage = reinterpret_cast<float*>(smp);   // mode 3 staging [col][132]
#pragma unroll
    for (int mt = 0; mt < MTC; mt++) {
#pragma unroll
        for (int nt = 0; nt < 4; nt++) {
            int col = wn * 32 + nt * 8 + tg * 2;
            float bv0 = __ldg(bias + oc0 + col);
            float bv1 = __ldg(bias + oc0 + col + 1);
            int r0 = mbase + mt * 16 + g, r1 = r0 + 8;
            float v00 = acc[mt][nt][0] + accc[mt][nt][0] * LO_INV + bv0;
            float v01 = acc[mt][nt][1] + accc[mt][nt][1] * LO_INV + bv1;
            float v10 = acc[mt][nt][2] + accc[mt][nt][2] * LO_INV + bv0;
            float v11 = acc[mt][nt][3] + accc[mt][nt][3] * LO_INV + bv1;
            if (relu) {
                v00 = fmaxf(v00, 0.f); v01 = fmaxf(v01, 0.f);
                v10 = fmaxf(v10, 0.f); v11 = fmaxf(v11, 0.f);
            }
            if (mode == 3) {
                stage[col * 132 + r0] = v00; stage[(col + 1) * 132 + r0] = v01;
                stage[col * 132 + r1] = v10; stage[(col + 1) * 132 + r1] = v11;
            } else if (out_f32 != nullptr) {
                *reinterpret_cast<float2*>(out_f32 + ((size_t)b * Tout + t0 + r0) * OC + oc0 + col) =
                    make_float2(v00, v01);
                *reinterpret_cast<float2*>(out_f32 + ((size_t)b * Tout + t0 + r1) * OC + oc0 + col) =
                    make_float2(v10, v11);
            } else {
                int tr0 = (mode == 2) ? (2 * (t0 + r0) + pair) : (t0 + r0);
                int tr1 = (mode == 2) ? (2 * (t0 + r1) + pair) : (t0 + r1);
                size_t o0 = ((size_t)b * Tout + tr0) * OC + oc0 + col;
                size_t o1 = ((size_t)b * Tout + tr1) * OC + oc0 + col;
                __half h00 = __float2half_rn(v00), h01 = __float2half_rn(v01);
                __half h10 = __float2half_rn(v10), h11 = __float2half_rn(v11);
                *reinterpret_cast<__half2*>(out_hi + o0) = __halves2half2(h00, h01);
                *reinterpret_cast<__half2*>(out_lo + o0) =
                    __halves2half2(__float2half_rn((v00 - __half2float(h00)) * LO_SCALE),
                                   __float2half_rn((v01 - __half2float(h01)) * LO_SCALE));
                *reinterpret_cast<__half2*>(out_hi + o1) = __halves2half2(h10, h11);
                *reinterpret_cast<__half2*>(out_lo + o1) =
                    __halves2half2(__float2half_rn((v10 - __half2float(h10)) * LO_SCALE),
                                   __float2half_rn((v11 - __half2float(h11)) * LO_SCALE));
            }
        }
    }
    if (mode == 3) {
        __syncthreads();
        // stage[col(oc_local)][m] -> out[b][oc0+col][2*(t0+m)+pair]
        for (int q = 0; q < 64; q++) {
            int idx = q * 256 + tid;
            int r = idx >> 7, m = idx & 127;
            out_f32[((size_t)(b * 256 + oc0 + r)) * 32768 + 2 * (t0 + m) + pair] =
                stage[r * 132 + m];
        }
    }
}

// ---------------- VQ: exact fp32 nearest code, q -> hi/lo fp16 ----------------
__global__ void __launch_bounds__(128)
vq_kernel(const float* __restrict__ z, const float* __restrict__ cb,
          const float* __restrict__ cnh,
          __half* __restrict__ qh, __half* __restrict__ ql) {
    extern __shared__ float cbs[];   // [512*64] codebook + [512] cnh
    int tid = threadIdx.x;
    for (int i = tid; i < 512 * 64 / 4; i += 128)
        reinterpret_cast<float4*>(cbs)[i] = reinterpret_cast<const float4*>(cb)[i];
    float* cns = cbs + 512 * 64;
    for (int i = tid; i < 512; i += 128) cns[i] = cnh[i];
    __syncthreads();

    int tg = blockIdx.x * 128 + tid;
    const float* zp = z + (size_t)tg * 64;
    float zr[64];
#pragma unroll
    for (int k = 0; k < 64; k++) zr[k] = zp[k];
    float best = -1e30f;
    int bi = 0;
    for (int c = 0; c < 512; c++) {
        const float* cr = cbs + c * 64;
        float dot = 0.f;
#pragma unroll
        for (int k = 0; k < 64; k++) dot = fmaf(zr[k], cr[k], dot);
        float s = dot - cns[c];
        if (s > best) { best = s; bi = c; }
    }
    const float* cw = cbs + bi * 64;
    __half2* oh = reinterpret_cast<__half2*>(qh + (size_t)tg * 64);
    __half2* ol = reinterpret_cast<__half2*>(ql + (size_t)tg * 64);
#pragma unroll
    for (int k = 0; k < 32; k++) {
        float a0 = cw[2 * k], a1 = cw[2 * k + 1];
        __half h0v = __float2half_rn(a0);
        __half h1v = __float2half_rn(a1);
        oh[k] = __halves2half2(h0v, h1v);
        ol[k] = __halves2half2(__float2half_rn((a0 - __half2float(h0v)) * LO_SCALE),
                               __float2half_rn((a1 - __half2float(h1v)) * LO_SCALE));
    }
}

// ---------------- launcher ----------------
extern "C" void kernel_launch(void* const* d_in, const int* in_sizes, int n_in,
                              void* d_out, int out_size) {
    (void)in_sizes; (void)n_in; (void)out_size;
    const float* inputs    = (const float*)d_in[0];
    const float* enc_w_in  = (const float*)d_in[1];
    const float* enc_b_in  = (const float*)d_in[2];
    const float* enc_ws    = (const float*)d_in[3];
    const float* enc_bs    = (const float*)d_in[4];
    const float* enc_w_out = (const float*)d_in[5];
    const float* enc_b_out = (const float*)d_in[6];
    const float* codebook  = (const float*)d_in[7];
    const float* dec_w_in  = (const float*)d_in[8];
    const float* dec_b_in  = (const float*)d_in[9];
    const float* dec_ws    = (const float*)d_in[10];
    const float* dec_bs    = (const float*)d_in[11];
    const float* dec_w_out = (const float*)d_in[12];
    const float* dec_b_out = (const float*)d_in[13];
    float* out = (float*)d_out;

    __half *h0, *l0, *h1, *l1, *qh, *ql, *wh, *wl;
    float *zT, *cnh;
    cudaGetSymbolAddress((void**)&h0, g_h0);
    cudaGetSymbolAddress((void**)&l0, g_l0);
    cudaGetSymbolAddress((void**)&h1, g_h1);
    cudaGetSymbolAddress((void**)&l1, g_l1);
    cudaGetSymbolAddress((void**)&zT, g_zT);
    cudaGetSymbolAddress((void**)&qh, g_qh);
    cudaGetSymbolAddress((void**)&ql, g_ql);
    cudaGetSymbolAddress((void**)&wh, g_whi);
    cudaGetSymbolAddress((void**)&wl, g_wlo);
    cudaGetSymbolAddress((void**)&cnh, g_cnh);

    const int GEMM_SMEM = 3 * 65536 + 1024;   // 3-stage pipeline + align
    const int VQ_SMEM = 512 * 64 * 4 + 512 * 4;
    cudaFuncSetAttribute(conv_mma_kernel<4>, cudaFuncAttributeMaxDynamicSharedMemorySize, GEMM_SMEM);
    cudaFuncSetAttribute(conv_mma_kernel<2>, cudaFuncAttributeMaxDynamicSharedMemorySize, GEMM_SMEM);
    cudaFuncSetAttribute(vq_kernel, cudaFuncAttributeMaxDynamicSharedMemorySize, VQ_SMEM);

    const int WSLOT = 196608;

    // Launch indices 4 AND 5 are heavy convs so ncu (-s 5 -c 1) captures a GEMM
    // regardless of 0/1-indexed skip convention.
    repack_kernel<<<768, 256>>>(enc_ws + 0 * 196608, wh + 0 * WSLOT, wl + 0 * WSLOT, 256, 256); // 0
    cb_prep_kernel<<<1, 512>>>(codebook, cnh);                                                   // 1
    e1_kernel<<<dim3(256, 16), 256>>>(inputs, enc_w_in, enc_b_in, h0, l0);                       // 2
    repack_kernel<<<768, 256>>>(enc_ws + 1 * 196608, wh + 1 * WSLOT, wl + 1 * WSLOT, 256, 256); // 3
    conv_mma_kernel<4><<<dim3(2, 64, 16), 256, GEMM_SMEM>>>(h0, l0, wh + 0 * WSLOT, wl + 0 * WSLOT,
        enc_bs + 0, h1, l1, nullptr, 256, 256, 16384, 8192, 1, 1);                               // 4
    conv_mma_kernel<4><<<dim3(2, 32, 16), 256, GEMM_SMEM>>>(h1, l1, wh + 1 * WSLOT, wl + 1 * WSLOT,
        enc_bs + 256, h0, l0, nullptr, 256, 256, 8192, 4096, 1, 1);                              // 5
    repack_kernel<<<768, 256>>>(enc_ws + 2 * 196608, wh + 2 * WSLOT, wl + 2 * WSLOT, 256, 256); // 6
    repack_kernel<<<192, 256>>>(enc_w_out, wh + 3 * WSLOT, wl + 3 * WSLOT, 64, 256);            // 7
    repack_kernel<<<192, 256>>>(dec_w_in, wh + 4 * WSLOT, wl + 4 * WSLOT, 256, 64);             // 8
    repack_kernel<<<768, 256>>>(dec_ws + 0 * 196608, wh + 5 * WSLOT, wl + 5 * WSLOT, 256, 256); // 9
    repack_kernel<<<768, 256>>>(dec_ws + 1 * 196608, wh + 6 * WSLOT, wl + 6 * WSLOT, 256, 256); // 10
    repack_kernel<<<768, 256>>>(dec_ws + 2 * 196608, wh + 7 * WSLOT, wl + 7 * WSLOT, 256, 256); // 11
    repack_kernel<<<768, 256>>>(dec_w_out, wh + 8 * WSLOT, wl + 8 * WSLOT, 256, 256);           // 12

    // ---- rest of encoder ----
    conv_mma_kernel<4><<<dim3(2, 16, 16), 256, GEMM_SMEM>>>(h0, l0, wh + 2 * WSLOT, wl + 2 * WSLOT,
        enc_bs + 512, h1, l1, nullptr, 256, 256, 4096, 2048, 1, 1);
    conv_mma_kernel<2><<<dim3(1, 16, 16), 256, GEMM_SMEM>>>(h1, l1, wh + 3 * WSLOT, wl + 3 * WSLOT,
        enc_b_out, nullptr, nullptr, zT, 256, 64, 2048, 2048, 0, 0);

    // ---- VQ ----
    vq_kernel<<<256, 128, VQ_SMEM>>>(zT, codebook, cnh, qh, ql);

    // ---- decoder ----
    conv_mma_kernel<4><<<dim3(2, 16, 16), 256, GEMM_SMEM>>>(qh, ql, wh + 4 * WSLOT, wl + 4 * WSLOT,
        dec_b_in, h0, l0, nullptr, 64, 256, 2048, 2048, 0, 1);
    conv_mma_kernel<4><<<dim3(4, 16, 16), 256, GEMM_SMEM>>>(h0, l0, wh + 5 * WSLOT, wl + 5 * WSLOT,
        dec_bs + 0, h1, l1, nullptr, 256, 256, 2048, 4096, 2, 1);
    conv_mma_kernel<4><<<dim3(4, 32, 16), 256, GEMM_SMEM>>>(h1, l1, wh + 6 * WSLOT, wl + 6 * WSLOT,
        dec_bs + 256, h0, l0, nullptr, 256, 256, 4096, 8192, 2, 1);
    conv_mma_kernel<4><<<dim3(4, 64, 16), 256, GEMM_SMEM>>>(h0, l0, wh + 7 * WSLOT, wl + 7 * WSLOT,
        dec_bs + 512, h1, l1, nullptr, 256, 256, 8192, 16384, 2, 1);
    conv_mma_kernel<4><<<dim3(4, 128, 16), 256, GEMM_SMEM>>>(h1, l1, wh + 8 * WSLOT, wl + 8 * WSLOT,
        dec_b_out, nullptr, nullptr, out, 256, 256, 16384, 32768, 3, 0);
}

// round 10
// speedup vs baseline: 1.1067x; 1.1067x over previous
#include <cuda_runtime.h>
#include <cuda_fp16.h>

typedef unsigned long long u64;
typedef unsigned int u32;
#define DI __device__ __forceinline__

#define LO_SCALE 2048.f
#define LO_INV (1.f / 2048.f)

// ---------------- static scratch ----------------
__device__ __half g_h0[16*16384*256];
__device__ __half g_l0[16*16384*256];
__device__ __half g_h1[16*16384*256];
__device__ __half g_l1[16*16384*256];
__device__ float  g_zT[16*2048*64];
__device__ __half g_qh[16*2048*64];
__device__ __half g_ql[16*2048*64];
__device__ __half g_whi[9*196608];
__device__ __half g_wlo[9*196608];
__device__ float  g_cnh[512];

// ---------------- PTX helpers ----------------
DI u32 smem_u32(const void* p) {
    u32 a;
    asm("{ .reg .u64 t; cvta.to.shared.u64 t, %1; cvt.u32.u64 %0, t; }" : "=r"(a) : "l"(p));
    return a;
}
DI void cpa16(u32 dst, const void* src, int src_sz) {
    asm volatile("cp.async.cg.shared.global [%0], [%1], 16, %2;"
                 :: "r"(dst), "l"(src), "r"(src_sz) : "memory");
}
DI void cpa_commit() { asm volatile("cp.async.commit_group;" ::: "memory"); }
DI void cpa_wait1() { asm volatile("cp.async.wait_group 1;" ::: "memory"); }
DI void cpa_wait0() { asm volatile("cp.async.wait_group 0;" ::: "memory"); }
DI void ldsm4(u32* r, u32 addr) {
    asm volatile("ldmatrix.sync.aligned.m8n8.x4.shared.b16 {%0,%1,%2,%3}, [%4];"
                 : "=r"(r[0]), "=r"(r[1]), "=r"(r[2]), "=r"(r[3]) : "r"(addr));
}
DI void mma16816(float* c, const u32* a, u32 b0, u32 b1) {
    asm volatile(
        "mma.sync.aligned.m16n8k16.row.col.f32.f16.f16.f32 "
        "{%0,%1,%2,%3}, {%4,%5,%6,%7}, {%8,%9}, {%0,%1,%2,%3};"
        : "+f"(c[0]), "+f"(c[1]), "+f"(c[2]), "+f"(c[3])
        : "r"(a[0]), "r"(a[1]), "r"(a[2]), "r"(a[3]), "r"(b0), "r"(b1));
}
DI u32 swz(u32 o) { return o ^ ((o >> 3) & 0x70); }

// ---------------- weight repack + split: w[oc][ic][k] -> [(k*nch+c)][oc][64] hi/lo ----------------
__global__ void repack_kernel(const float* __restrict__ w, __half* __restrict__ wh,
                              __half* __restrict__ wl, int OC, int IC) {
    int i = blockIdx.x * 256 + threadIdx.x;
    int n = OC * IC * 3;
    if (i >= n) return;
    int oc = i / (IC * 3);
    int r = i - oc * IC * 3;
    int ic = r / 3, k = r - ic * 3;
    int nch = IC >> 6, c = ic >> 6, j = ic & 63;
    float v = w[i];
    __half h = __float2half_rn(v);
    size_t d = ((size_t)(k * nch + c) * OC + oc) * 64 + j;
    wh[d] = h;
    wl[d] = __float2half_rn((v - __half2float(h)) * LO_SCALE);
}

__global__ void cb_prep_kernel(const float* __restrict__ cb, float* __restrict__ cnh) {
    int c = threadIdx.x;
    float s = 0.f;
    for (int k = 0; k < 64; k++) { float v = cb[c * 64 + k]; s += v * v; }
    cnh[c] = 0.5f * s;
}

// ---------------- encoder layer 1: IC=1, stride 2, relu, t-major hi/lo out ----------------
__global__ void e1_kernel(const float* __restrict__ x, const float* __restrict__ w,
                          const float* __restrict__ bias,
                          __half* __restrict__ oh, __half* __restrict__ ol) {
    __shared__ float xs[132];
    int b = blockIdx.y, tc = blockIdx.x * 64, tid = threadIdx.x;
    const float* xr = x + (size_t)b * 32768;
    for (int i = tid; i < 130; i += 256) {
        int pos = 2 * tc - 1 + i;
        xs[i] = (pos >= 0 && pos < 32768) ? xr[pos] : 0.f;
    }
    __syncthreads();
    float w0 = w[tid * 3], w1 = w[tid * 3 + 1], w2 = w[tid * 3 + 2], bv = bias[tid];
    for (int j = 0; j < 64; j++) {
        float v = fmaxf(bv + w0 * xs[2 * j] + w1 * xs[2 * j + 1] + w2 * xs[2 * j + 2], 0.f);
        __half h = __float2half_rn(v);
        size_t o = ((size_t)b * 16384 + tc + j) * 256 + tid;
        oh[o] = h;
        ol[o] = __float2half_rn((v - __half2float(h)) * LO_SCALE);
    }
}

// ---------------- generic mma.sync conv GEMM (fp16-split, scaled residuals) ----------------
// mode: 0=s1 conv, 1=s2 conv, 2=convT (pair-split), 3=convT final (fp32 ch-major out)
// grid: x = oc-tile (+pair for mode>=2), y = t-tile (BM rows), z = batch
// CTA tile BM x BN, 8 warps of 32x32 warp tiles, 2 CTAs/SM.
template <int BM, int BN>
__global__ void __launch_bounds__(256, 2)
conv_mma_kernel(const __half* __restrict__ in_hi, const __half* __restrict__ in_lo,
                const __half* __restrict__ w_hi, const __half* __restrict__ w_lo,
                const float* __restrict__ bias,
                __half* __restrict__ out_hi, __half* __restrict__ out_lo,
                float* __restrict__ out_f32,
                int IC, int OC, int Tin, int Tout, int mode, int relu) {
    const int WN = BN / 32;              // warps along N
    const int ASZ = BM * 128;            // bytes per A hi tile (BM x 64ic x 2B)
    const int BSZ = BN * 128;
    const int STAGE = 2 * (ASZ + BSZ);   // hi+lo for A and B = 48KB

    extern __shared__ char smraw[];
    u32 sb0 = smem_u32(smraw);
    u32 sb = (sb0 + 1023) & ~1023u;
    char* smp = smraw + (sb - sb0);

    const int tid = threadIdx.x, lane = tid & 31, wid = tid >> 5;
    const int t0 = blockIdx.y * BM;
    int xb = blockIdx.x;
    int oc0, pair;
    if (mode >= 2) { oc0 = (xb & 1) * 128; pair = xb >> 1; }
    else           { oc0 = xb * BN; pair = 0; }
    const int b = blockIdx.z;
    const int nch = IC >> 6;
    const int nsub = (mode < 2) ? 3 * nch : (pair ? 2 * nch : nch);
    const size_t inb = (size_t)b * Tin * IC;

    const int wm = wid / WN, wn = wid % WN;
    const int mbase = wm * 32;

    float acc[2][4][4];    // hi*hi
    float accc[2][4][4];   // cross terms (scaled by LO_SCALE)
#pragma unroll
    for (int mt = 0; mt < 2; mt++)
#pragma unroll
        for (int nt = 0; nt < 4; nt++)
#pragma unroll
            for (int k = 0; k < 4; k++) { acc[mt][nt][k] = 0.f; accc[mt][nt][k] = 0.f; }

    auto geo = [&](int i, int& c, int& kap, int& del) {
        if (mode < 2) { c = i / 3; int s = i - 3 * c; kap = s; del = s - 1; }
        else if (!pair) { c = i; kap = 1; del = 0; }
        else { c = i >> 1; if (i & 1) { kap = 2; del = 1; } else { kap = 0; del = 0; } }
    };
    // stage p: A_hi @0, A_lo @ASZ, B_hi @2*ASZ, B_lo @2*ASZ+BSZ
    auto load_chunk = [&](int i, int p) {
        int c, kap, del;
        geo(i, c, kap, del);
        u32 abase = sb + p * STAGE;
        u32 bbase = abase + 2 * ASZ;
        int r0 = tid >> 3, qd = tid & 7;
        const __half* sH = in_hi + inb + c * 64 + qd * 8;
        const __half* sL = in_lo + inb + c * 64 + qd * 8;
#pragma unroll
        for (int it = 0; it < BM / 32; it++) {
            int r = r0 + it * 32;
            int g = (mode == 1) ? (2 * (t0 + r) + del) : (t0 + r + del);
            int ok = (g >= 0 && g < Tin) ? 16 : 0;
            int gc = ok ? g : 0;
            u32 so = swz((u32)(r * 128 + qd * 16));
            cpa16(abase + so, sH + (size_t)gc * IC, ok);
            cpa16(abase + ASZ + so, sL + (size_t)gc * IC, ok);
        }
        const __half* wH = w_hi + ((size_t)(kap * nch + c) * OC + oc0) * 64 + qd * 8;
        const __half* wL = w_lo + ((size_t)(kap * nch + c) * OC + oc0) * 64 + qd * 8;
#pragma unroll
        for (int it = 0; it < BN / 32; it++) {
            int r = r0 + it * 32;
            u32 so = swz((u32)(r * 128 + qd * 16));
            cpa16(bbase + so, wH + (size_t)r * 64, 16);
            cpa16(bbase + BSZ + so, wL + (size_t)r * 64, 16);
        }
    };

    // double-buffer prologue
    load_chunk(0, 0);
    cpa_commit();
    if (nsub > 1) { load_chunk(1, 1); cpa_commit(); }

    for (int i = 0; i < nsub; i++) {
        int p = i & 1;
        if (i + 1 < nsub) cpa_wait1(); else cpa_wait0();
        __syncthreads();                       // chunk i visible to all threads

        u32 abase = sb + p * STAGE;
        u32 bbase = abase + 2 * ASZ;
#pragma unroll
        for (int ks = 0; ks < 4; ks++) {
            u32 bh[8], bl[8];
#pragma unroll
            for (int q = 0; q < 2; q++) {
                int brow = wn * 32 + q * 16 + ((lane >> 4) & 1) * 8 + (lane & 7);
                int bkb = ks * 32 + ((lane >> 3) & 1) * 16;
                u32 bad = bbase + swz((u32)(brow * 128 + bkb));
                ldsm4(&bh[q * 4], bad);
                ldsm4(&bl[q * 4], bad + BSZ);
            }
            int arow = mbase + (lane & 15);
            int akb = ks * 32 + (lane >> 4) * 16;
            u32 ah[2][4], al[2][4];
#pragma unroll
            for (int mt = 0; mt < 2; mt++) {
                u32 aad = abase + swz((u32)((arow + mt * 16) * 128 + akb));
                ldsm4(ah[mt], aad);
                ldsm4(al[mt], aad + ASZ);
            }
            // Phase 1: hh
#pragma unroll
            for (int mt = 0; mt < 2; mt++)
#pragma unroll
                for (int nt = 0; nt < 4; nt++) {
                    int bi = (nt >> 1) * 4 + (nt & 1) * 2;
                    mma16816(acc[mt][nt], ah[mt], bh[bi], bh[bi + 1]);
                }
            // Phase 2: hi*lo
#pragma unroll
            for (int mt = 0; mt < 2; mt++)
#pragma unroll
                for (int nt = 0; nt < 4; nt++) {
                    int bi = (nt >> 1) * 4 + (nt & 1) * 2;
                    mma16816(accc[mt][nt], ah[mt], bl[bi], bl[bi + 1]);
                }
            // Phase 3: lo*hi
#pragma unroll
            for (int mt = 0; mt < 2; mt++)
#pragma unroll
                for (int nt = 0; nt < 4; nt++) {
                    int bi = (nt >> 1) * 4 + (nt & 1) * 2;
                    mma16816(accc[mt][nt], al[mt], bh[bi], bh[bi + 1]);
                }
        }
        __syncthreads();                       // stage p fully consumed by all
        if (i + 2 < nsub) { load_chunk(i + 2, p); cpa_commit(); }
    }

    // ---------------- epilogue ----------------
    int g = lane >> 2, tg = lane & 3;
    float* stage = reinterpret_cast<float*>(smp);   // mode 3 staging [col][68]
#pragma unroll
    for (int mt = 0; mt < 2; mt++) {
#pragma unroll
        for (int nt = 0; nt < 4; nt++) {
            int col = wn * 32 + nt * 8 + tg * 2;
            float bv0 = __ldg(bias + oc0 + col);
            float bv1 = __ldg(bias + oc0 + col + 1);
            int r0 = mbase + mt * 16 + g, r1 = r0 + 8;
            float v00 = acc[mt][nt][0] + accc[mt][nt][0] * LO_INV + bv0;
            float v01 = acc[mt][nt][1] + accc[mt][nt][1] * LO_INV + bv1;
            float v10 = acc[mt][nt][2] + accc[mt][nt][2] * LO_INV + bv0;
            float v11 = acc[mt][nt][3] + accc[mt][nt][3] * LO_INV + bv1;
            if (relu) {
                v00 = fmaxf(v00, 0.f); v01 = fmaxf(v01, 0.f);
                v10 = fmaxf(v10, 0.f); v11 = fmaxf(v11, 0.f);
            }
            if (mode == 3) {
                stage[col * 68 + r0] = v00; stage[(col + 1) * 68 + r0] = v01;
                stage[col * 68 + r1] = v10; stage[(col + 1) * 68 + r1] = v11;
            } else if (out_f32 != nullptr) {
                *reinterpret_cast<float2*>(out_f32 + ((size_t)b * Tout + t0 + r0) * OC + oc0 + col) =
                    make_float2(v00, v01);
                *reinterpret_cast<float2*>(out_f32 + ((size_t)b * Tout + t0 + r1) * OC + oc0 + col) =
                    make_float2(v10, v11);
            } else {
                int tr0 = (mode == 2) ? (2 * (t0 + r0) + pair) : (t0 + r0);
                int tr1 = (mode == 2) ? (2 * (t0 + r1) + pair) : (t0 + r1);
                size_t o0 = ((size_t)b * Tout + tr0) * OC + oc0 + col;
                size_t o1 = ((size_t)b * Tout + tr1) * OC + oc0 + col;
                __half h00 = __float2half_rn(v00), h01 = __float2half_rn(v01);
                __half h10 = __float2half_rn(v10), h11 = __float2half_rn(v11);
                *reinterpret_cast<__half2*>(out_hi + o0) = __halves2half2(h00, h01);
                *reinterpret_cast<__half2*>(out_lo + o0) =
                    __halves2half2(__float2half_rn((v00 - __half2float(h00)) * LO_SCALE),
                                   __float2half_rn((v01 - __half2float(h01)) * LO_SCALE));
                *reinterpret_cast<__half2*>(out_hi + o1) = __halves2half2(h10, h11);
                *reinterpret_cast<__half2*>(out_lo + o1) =
                    __halves2half2(__float2half_rn((v10 - __half2float(h10)) * LO_SCALE),
                                   __float2half_rn((v11 - __half2float(h11)) * LO_SCALE));
            }
        }
    }
    if (mode == 3) {
        __syncthreads();
        // stage[col(oc_local)][m] -> out[b][oc0+col][2*(t0+m)+pair], BM=64
        for (int q = 0; q < 32; q++) {
            int idx = q * 256 + tid;
            int r = idx >> 6, m = idx & 63;
            out_f32[((size_t)(b * 256 + oc0 + r)) * 32768 + 2 * (t0 + m) + pair] =
                stage[r * 68 + m];
        }
    }
}

// ---------------- VQ: exact fp32 nearest code, q -> hi/lo fp16 ----------------
__global__ void __launch_bounds__(128)
vq_kernel(const float* __restrict__ z, const float* __restrict__ cb,
          const float* __restrict__ cnh,
          __half* __restrict__ qh, __half* __restrict__ ql) {
    extern __shared__ float cbs[];   // [512*64] codebook + [512] cnh
    int tid = threadIdx.x;
    for (int i = tid; i < 512 * 64 / 4; i += 128)
        reinterpret_cast<float4*>(cbs)[i] = reinterpret_cast<const float4*>(cb)[i];
    float* cns = cbs + 512 * 64;
    for (int i = tid; i < 512; i += 128) cns[i] = cnh[i];
    __syncthreads();

    int tg = blockIdx.x * 128 + tid;
    const float* zp = z + (size_t)tg * 64;
    float zr[64];
#pragma unroll
    for (int k = 0; k < 64; k++) zr[k] = zp[k];
    float best = -1e30f;
    int bi = 0;
    for (int c = 0; c < 512; c++) {
        const float* cr = cbs + c * 64;
        float dot = 0.f;
#pragma unroll
        for (int k = 0; k < 64; k++) dot = fmaf(zr[k], cr[k], dot);
        float s = dot - cns[c];
        if (s > best) { best = s; bi = c; }
    }
    const float* cw = cbs + bi * 64;
    __half2* oh = reinterpret_cast<__half2*>(qh + (size_t)tg * 64);
    __half2* ol = reinterpret_cast<__half2*>(ql + (size_t)tg * 64);
#pragma unroll
    for (int k = 0; k < 32; k++) {
        float a0 = cw[2 * k], a1 = cw[2 * k + 1];
        __half h0v = __float2half_rn(a0);
        __half h1v = __float2half_rn(a1);
        oh[k] = __halves2half2(h0v, h1v);
        ol[k] = __halves2half2(__float2half_rn((a0 - __half2float(h0v)) * LO_SCALE),
                               __float2half_rn((a1 - __half2float(h1v)) * LO_SCALE));
    }
}

// ---------------- launcher ----------------
extern "C" void kernel_launch(void* const* d_in, const int* in_sizes, int n_in,
                              void* d_out, int out_size) {
    (void)in_sizes; (void)n_in; (void)out_size;
    const float* inputs    = (const float*)d_in[0];
    const float* enc_w_in  = (const float*)d_in[1];
    const float* enc_b_in  = (const float*)d_in[2];
    const float* enc_ws    = (const float*)d_in[3];
    const float* enc_bs    = (const float*)d_in[4];
    const float* enc_w_out = (const float*)d_in[5];
    const float* enc_b_out = (const float*)d_in[6];
    const float* codebook  = (const float*)d_in[7];
    const float* dec_w_in  = (const float*)d_in[8];
    const float* dec_b_in  = (const float*)d_in[9];
    const float* dec_ws    = (const float*)d_in[10];
    const float* dec_bs    = (const float*)d_in[11];
    const float* dec_w_out = (const float*)d_in[12];
    const float* dec_b_out = (const float*)d_in[13];
    float* out = (float*)d_out;

    __half *h0, *l0, *h1, *l1, *qh, *ql, *wh, *wl;
    float *zT, *cnh;
    cudaGetSymbolAddress((void**)&h0, g_h0);
    cudaGetSymbolAddress((void**)&l0, g_l0);
    cudaGetSymbolAddress((void**)&h1, g_h1);
    cudaGetSymbolAddress((void**)&l1, g_l1);
    cudaGetSymbolAddress((void**)&zT, g_zT);
    cudaGetSymbolAddress((void**)&qh, g_qh);
    cudaGetSymbolAddress((void**)&ql, g_ql);
    cudaGetSymbolAddress((void**)&wh, g_whi);
    cudaGetSymbolAddress((void**)&wl, g_wlo);
    cudaGetSymbolAddress((void**)&cnh, g_cnh);

    const int GEMM_SMEM = 2 * 49152 + 1024;   // 2 stages of 48KB + align = 99328
    const int VQ_SMEM = 512 * 64 * 4 + 512 * 4;
    cudaFuncSetAttribute(conv_mma_kernel<64, 128>, cudaFuncAttributeMaxDynamicSharedMemorySize, GEMM_SMEM);
    cudaFuncSetAttribute(conv_mma_kernel<128, 64>, cudaFuncAttributeMaxDynamicSharedMemorySize, GEMM_SMEM);
    cudaFuncSetAttribute(vq_kernel, cudaFuncAttributeMaxDynamicSharedMemorySize, VQ_SMEM);

    const int WSLOT = 196608;

    // Launch indices 4 AND 5 are heavy convs so ncu captures a GEMM either way.
    repack_kernel<<<768, 256>>>(enc_ws + 0 * 196608, wh + 0 * WSLOT, wl + 0 * WSLOT, 256, 256); // 0
    cb_prep_kernel<<<1, 512>>>(codebook, cnh);                                                   // 1
    e1_kernel<<<dim3(256, 16), 256>>>(inputs, enc_w_in, enc_b_in, h0, l0);                       // 2
    repack_kernel<<<768, 256>>>(enc_ws + 1 * 196608, wh + 1 * WSLOT, wl + 1 * WSLOT, 256, 256); // 3
    conv_mma_kernel<64, 128><<<dim3(2, 128, 16), 256, GEMM_SMEM>>>(h0, l0, wh + 0 * WSLOT, wl + 0 * WSLOT,
        enc_bs + 0, h1, l1, nullptr, 256, 256, 16384, 8192, 1, 1);                               // 4
    conv_mma_kernel<64, 128><<<dim3(2, 64, 16), 256, GEMM_SMEM>>>(h1, l1, wh + 1 * WSLOT, wl + 1 * WSLOT,
        enc_bs + 256, h0, l0, nullptr, 256, 256, 8192, 4096, 1, 1);                              // 5
    repack_kernel<<<768, 256>>>(enc_ws + 2 * 196608, wh + 2 * WSLOT, wl + 2 * WSLOT, 256, 256); // 6
    repack_kernel<<<192, 256>>>(enc_w_out, wh + 3 * WSLOT, wl + 3 * WSLOT, 64, 256);            // 7
    repack_kernel<<<192, 256>>>(dec_w_in, wh + 4 * WSLOT, wl + 4 * WSLOT, 256, 64);             // 8
    repack_kernel<<<768, 256>>>(dec_ws + 0 * 196608, wh + 5 * WSLOT, wl + 5 * WSLOT, 256, 256); // 9
    repack_kernel<<<768, 256>>>(dec_ws + 1 * 196608, wh + 6 * WSLOT, wl + 6 * WSLOT, 256, 256); // 10
    repack_kernel<<<768, 256>>>(dec_ws + 2 * 196608, wh + 7 * WSLOT, wl + 7 * WSLOT, 256, 256); // 11
    repack_kernel<<<768, 256>>>(dec_w_out, wh + 8 * WSLOT, wl + 8 * WSLOT, 256, 256);           // 12

    // ---- rest of encoder ----
    conv_mma_kernel<64, 128><<<dim3(2, 32, 16), 256, GEMM_SMEM>>>(h0, l0, wh + 2 * WSLOT, wl + 2 * WSLOT,
        enc_bs + 512, h1, l1, nullptr, 256, 256, 4096, 2048, 1, 1);
    conv_mma_kernel<128, 64><<<dim3(1, 16, 16), 256, GEMM_SMEM>>>(h1, l1, wh + 3 * WSLOT, wl + 3 * WSLOT,
        enc_b_out, nullptr, nullptr, zT, 256, 64, 2048, 2048, 0, 0);

    // ---- VQ ----
    vq_kernel<<<256, 128, VQ_SMEM>>>(zT, codebook, cnh, qh, ql);

    // ---- decoder ----
    conv_mma_kernel<64, 128><<<dim3(2, 32, 16), 256, GEMM_SMEM>>>(qh, ql, wh + 4 * WSLOT, wl + 4 * WSLOT,
        dec_b_in, h0, l0, nullptr, 64, 256, 2048, 2048, 0, 1);
    conv_mma_kernel<64, 128><<<dim3(4, 32, 16), 256, GEMM_SMEM>>>(h0, l0, wh + 5 * WSLOT, wl + 5 * WSLOT,
        dec_bs + 0, h1, l1, nullptr, 256, 256, 2048, 4096, 2, 1);
    conv_mma_kernel<64, 128><<<dim3(4, 64, 16), 256, GEMM_SMEM>>>(h1, l1, wh + 6 * WSLOT, wl + 6 * WSLOT,
        dec_bs + 256, h0, l0, nullptr, 256, 256, 4096, 8192, 2, 1);
    conv_mma_kernel<64, 128><<<dim3(4, 128, 16), 256, GEMM_SMEM>>>(h0, l0, wh + 7 * WSLOT, wl + 7 * WSLOT,
        dec_bs + 512, h1, l1, nullptr, 256, 256, 8192, 16384, 2, 1);
    conv_mma_kernel<64, 128><<<dim3(4, 256, 16), 256, GEMM_SMEM>>>(h1, l1, wh + 8 * WSLOT, wl + 8 * WSLOT,
        dec_b_out, nullptr, nullptr, out, 256, 256, 16384, 32768, 3, 0);
}

// round 11
// speedup vs baseline: 1.1096x; 1.0026x over previous
#include <cuda_runtime.h>
#include <cuda_fp16.h>

typedef unsigned long long u64;
typedef unsigned int u32;
#define DI __device__ __forceinline__

#define LO_SCALE 2048.f
#define LO_INV (1.f / 2048.f)

// ---------------- static scratch ----------------
__device__ __half g_h0[16*16384*256];
__device__ __half g_l0[16*16384*256];
__device__ __half g_h1[16*16384*256];
__device__ __half g_l1[16*16384*256];
__device__ float  g_zT[16*2048*64];
__device__ __half g_qh[16*2048*64];
__device__ __half g_ql[16*2048*64];
__device__ __half g_whi[9*196608];
__device__ __half g_wlo[9*196608];
__device__ float  g_cnh[512];

// ---------------- PTX helpers ----------------
DI u32 smem_u32(const void* p) {
    u32 a;
    asm("{ .reg .u64 t; cvta.to.shared.u64 t, %1; cvt.u32.u64 %0, t; }" : "=r"(a) : "l"(p));
    return a;
}
DI void cpa16(u32 dst, const void* src, int src_sz) {
    asm volatile("cp.async.cg.shared.global [%0], [%1], 16, %2;"
                 :: "r"(dst), "l"(src), "r"(src_sz) : "memory");
}
DI void cpa_commit() { asm volatile("cp.async.commit_group;" ::: "memory"); }
DI void cpa_wait1() { asm volatile("cp.async.wait_group 1;" ::: "memory"); }
DI void cpa_wait0() { asm volatile("cp.async.wait_group 0;" ::: "memory"); }
DI void ldsm4(u32* r, u32 addr) {
    asm volatile("ldmatrix.sync.aligned.m8n8.x4.shared.b16 {%0,%1,%2,%3}, [%4];"
                 : "=r"(r[0]), "=r"(r[1]), "=r"(r[2]), "=r"(r[3]) : "r"(addr));
}
DI void mma16816(float* c, const u32* a, u32 b0, u32 b1) {
    asm volatile(
        "mma.sync.aligned.m16n8k16.row.col.f32.f16.f16.f32 "
        "{%0,%1,%2,%3}, {%4,%5,%6,%7}, {%8,%9}, {%0,%1,%2,%3};"
        : "+f"(c[0]), "+f"(c[1]), "+f"(c[2]), "+f"(c[3])
        : "r"(a[0]), "r"(a[1]), "r"(a[2]), "r"(a[3]), "r"(b0), "r"(b1));
}
DI u32 swz(u32 o) { return o ^ ((o >> 3) & 0x70); }

// ---------------- single merged weight repack: all 9 slots ----------------
// w[oc][ic][k] -> wt[slot][(k*nch+c)][oc][64] hi/lo
__global__ void repack_all_kernel(const float* __restrict__ enc_ws,
                                  const float* __restrict__ enc_w_out,
                                  const float* __restrict__ dec_w_in,
                                  const float* __restrict__ dec_ws,
                                  const float* __restrict__ dec_w_out,
                                  __half* __restrict__ wh, __half* __restrict__ wl) {
    const int WSLOT = 196608;
    int slot = blockIdx.y;
    const float* src;
    int OC, IC;
    if (slot < 3)       { src = enc_ws + slot * 196608;       OC = 256; IC = 256; }
    else if (slot == 3) { src = enc_w_out;                    OC = 64;  IC = 256; }
    else if (slot == 4) { src = dec_w_in;                     OC = 256; IC = 64;  }
    else if (slot < 8)  { src = dec_ws + (slot - 5) * 196608; OC = 256; IC = 256; }
    else                { src = dec_w_out;                    OC = 256; IC = 256; }

    int i = blockIdx.x * 256 + threadIdx.x;
    int n = OC * IC * 3;
    if (i >= n) return;
    int oc = i / (IC * 3);
    int r = i - oc * IC * 3;
    int ic = r / 3, k = r - ic * 3;
    int nch = IC >> 6, c = ic >> 6, j = ic & 63;
    float v = src[i];
    __half h = __float2half_rn(v);
    size_t d = (size_t)slot * WSLOT + ((size_t)(k * nch + c) * OC + oc) * 64 + j;
    wh[d] = h;
    wl[d] = __float2half_rn((v - __half2float(h)) * LO_SCALE);
}

__global__ void cb_prep_kernel(const float* __restrict__ cb, float* __restrict__ cnh) {
    int c = threadIdx.x;
    float s = 0.f;
    for (int k = 0; k < 64; k++) { float v = cb[c * 64 + k]; s += v * v; }
    cnh[c] = 0.5f * s;
}

// ---------------- encoder layer 1: IC=1, stride 2, relu, t-major hi/lo out ----------------
__global__ void e1_kernel(const float* __restrict__ x, const float* __restrict__ w,
                          const float* __restrict__ bias,
                          __half* __restrict__ oh, __half* __restrict__ ol) {
    __shared__ float xs[132];
    int b = blockIdx.y, tc = blockIdx.x * 64, tid = threadIdx.x;
    const float* xr = x + (size_t)b * 32768;
    for (int i = tid; i < 130; i += 256) {
        int pos = 2 * tc - 1 + i;
        xs[i] = (pos >= 0 && pos < 32768) ? xr[pos] : 0.f;
    }
    __syncthreads();
    float w0 = w[tid * 3], w1 = w[tid * 3 + 1], w2 = w[tid * 3 + 2], bv = bias[tid];
    for (int j = 0; j < 64; j++) {
        float v = fmaxf(bv + w0 * xs[2 * j] + w1 * xs[2 * j + 1] + w2 * xs[2 * j + 2], 0.f);
        __half h = __float2half_rn(v);
        size_t o = ((size_t)b * 16384 + tc + j) * 256 + tid;
        oh[o] = h;
        ol[o] = __float2half_rn((v - __half2float(h)) * LO_SCALE);
    }
}

// ---------------- generic mma.sync conv GEMM (fp16-split, scaled residuals) ----------------
// mode: 0=s1 conv, 1=s2 conv, 2=convT (pair-split), 3=convT final (fp32 ch-major out)
// grid: x = oc-tile (+pair for mode>=2), y = t-tile (BM rows), z = batch
// CTA tile BM x BN, 8 warps of 32x32 warp tiles, 2 CTAs/SM.
template <int BM, int BN>
__global__ void __launch_bounds__(256, 2)
conv_mma_kernel(const __half* __restrict__ in_hi, const __half* __restrict__ in_lo,
                const __half* __restrict__ w_hi, const __half* __restrict__ w_lo,
                const float* __restrict__ bias,
                __half* __restrict__ out_hi, __half* __restrict__ out_lo,
                float* __restrict__ out_f32,
                int IC, int OC, int Tin, int Tout, int mode, int relu) {
    const int WN = BN / 32;              // warps along N
    const int ASZ = BM * 128;            // bytes per A hi tile (BM x 64ic x 2B)
    const int BSZ = BN * 128;
    const int STAGE = 2 * (ASZ + BSZ);   // hi+lo for A and B = 48KB

    extern __shared__ char smraw[];
    u32 sb0 = smem_u32(smraw);
    u32 sb = (sb0 + 1023) & ~1023u;
    char* smp = smraw + (sb - sb0);

    const int tid = threadIdx.x, lane = tid & 31, wid = tid >> 5;
    const int t0 = blockIdx.y * BM;
    int xb = blockIdx.x;
    int oc0, pair;
    if (mode >= 2) { oc0 = (xb & 1) * 128; pair = xb >> 1; }
    else           { oc0 = xb * BN; pair = 0; }
    const int b = blockIdx.z;
    const int nch = IC >> 6;
    const int nsub = (mode < 2) ? 3 * nch : (pair ? 2 * nch : nch);
    const size_t inb = (size_t)b * Tin * IC;

    const int wm = wid / WN, wn = wid % WN;
    const int mbase = wm * 32;

    float acc[2][4][4];    // hi*hi
    float accc[2][4][4];   // cross terms (scaled by LO_SCALE)
#pragma unroll
    for (int mt = 0; mt < 2; mt++)
#pragma unroll
        for (int nt = 0; nt < 4; nt++)
#pragma unroll
            for (int k = 0; k < 4; k++) { acc[mt][nt][k] = 0.f; accc[mt][nt][k] = 0.f; }

    auto geo = [&](int i, int& c, int& kap, int& del) {
        if (mode < 2) { c = i / 3; int s = i - 3 * c; kap = s; del = s - 1; }
        else if (!pair) { c = i; kap = 1; del = 0; }
        else { c = i >> 1; if (i & 1) { kap = 2; del = 1; } else { kap = 0; del = 0; } }
    };
    // stage p: A_hi @0, A_lo @ASZ, B_hi @2*ASZ, B_lo @2*ASZ+BSZ
    auto load_chunk = [&](int i, int p) {
        int c, kap, del;
        geo(i, c, kap, del);
        u32 abase = sb + p * STAGE;
        u32 bbase = abase + 2 * ASZ;
        int r0 = tid >> 3, qd = tid & 7;
        const __half* sH = in_hi + inb + c * 64 + qd * 8;
        const __half* sL = in_lo + inb + c * 64 + qd * 8;
#pragma unroll
        for (int it = 0; it < BM / 32; it++) {
            int r = r0 + it * 32;
            int g = (mode == 1) ? (2 * (t0 + r) + del) : (t0 + r + del);
            int ok = (g >= 0 && g < Tin) ? 16 : 0;
            int gc = ok ? g : 0;
            u32 so = swz((u32)(r * 128 + qd * 16));
            cpa16(abase + so, sH + (size_t)gc * IC, ok);
            cpa16(abase + ASZ + so, sL + (size_t)gc * IC, ok);
        }
        const __half* wH = w_hi + ((size_t)(kap * nch + c) * OC + oc0) * 64 + qd * 8;
        const __half* wL = w_lo + ((size_t)(kap * nch + c) * OC + oc0) * 64 + qd * 8;
#pragma unroll
        for (int it = 0; it < BN / 32; it++) {
            int r = r0 + it * 32;
            u32 so = swz((u32)(r * 128 + qd * 16));
            cpa16(bbase + so, wH + (size_t)r * 64, 16);
            cpa16(bbase + BSZ + so, wL + (size_t)r * 64, 16);
        }
    };

    // double-buffer prologue
    load_chunk(0, 0);
    cpa_commit();
    if (nsub > 1) { load_chunk(1, 1); cpa_commit(); }

    for (int i = 0; i < nsub; i++) {
        int p = i & 1;
        if (i + 1 < nsub) cpa_wait1(); else cpa_wait0();
        __syncthreads();                       // chunk i visible to all threads

        u32 abase = sb + p * STAGE;
        u32 bbase = abase + 2 * ASZ;
#pragma unroll
        for (int ks = 0; ks < 4; ks++) {
            int arow = mbase + (lane & 15);
            int akb = ks * 32 + (lane >> 4) * 16;
            u32 aad0 = abase + swz((u32)(arow * 128 + akb));
            u32 aad1 = abase + swz((u32)((arow + 16) * 128 + akb));

            // A-hi and B-hi fragments
            u32 af[2][4];     // holds ah, then reused for al
            u32 bh[8];
            ldsm4(af[0], aad0);
            ldsm4(af[1], aad1);
#pragma unroll
            for (int q = 0; q < 2; q++) {
                int brow = wn * 32 + q * 16 + ((lane >> 4) & 1) * 8 + (lane & 7);
                int bkb = ks * 32 + ((lane >> 3) & 1) * 16;
                ldsm4(&bh[q * 4], bbase + swz((u32)(brow * 128 + bkb)));
            }
            // Phase 1: hh (A-hi x B-hi)
#pragma unroll
            for (int mt = 0; mt < 2; mt++)
#pragma unroll
                for (int nt = 0; nt < 4; nt++) {
                    int bi = (nt >> 1) * 4 + (nt & 1) * 2;
                    mma16816(acc[mt][nt], af[mt], bh[bi], bh[bi + 1]);
                }
            // B-lo fragments
            u32 bl[8];
#pragma unroll
            for (int q = 0; q < 2; q++) {
                int brow = wn * 32 + q * 16 + ((lane >> 4) & 1) * 8 + (lane & 7);
                int bkb = ks * 32 + ((lane >> 3) & 1) * 16;
                ldsm4(&bl[q * 4], bbase + BSZ + swz((u32)(brow * 128 + bkb)));
            }
            // Phase 2: A-hi x B-lo (af dies after this phase)
#pragma unroll
            for (int mt = 0; mt < 2; mt++)
#pragma unroll
                for (int nt = 0; nt < 4; nt++) {
                    int bi = (nt >> 1) * 4 + (nt & 1) * 2;
                    mma16816(accc[mt][nt], af[mt], bl[bi], bl[bi + 1]);
                }
            // reload A-lo into the SAME fragment registers
            ldsm4(af[0], aad0 + ASZ);
            ldsm4(af[1], aad1 + ASZ);
            // Phase 3: A-lo x B-hi
#pragma unroll
            for (int mt = 0; mt < 2; mt++)
#pragma unroll
                for (int nt = 0; nt < 4; nt++) {
                    int bi = (nt >> 1) * 4 + (nt & 1) * 2;
                    mma16816(accc[mt][nt], af[mt], bh[bi], bh[bi + 1]);
                }
        }
        __syncthreads();                       // stage p fully consumed by all
        if (i + 2 < nsub) { load_chunk(i + 2, p); cpa_commit(); }
    }

    // ---------------- epilogue ----------------
    int g = lane >> 2, tg = lane & 3;
    float* stage = reinterpret_cast<float*>(smp);   // mode 3 staging [col][68]
#pragma unroll
    for (int mt = 0; mt < 2; mt++) {
#pragma unroll
        for (int nt = 0; nt < 4; nt++) {
            int col = wn * 32 + nt * 8 + tg * 2;
            float bv0 = __ldg(bias + oc0 + col);
            float bv1 = __ldg(bias + oc0 + col + 1);
            int r0 = mbase + mt * 16 + g, r1 = r0 + 8;
            float v00 = acc[mt][nt][0] + accc[mt][nt][0] * LO_INV + bv0;
            float v01 = acc[mt][nt][1] + accc[mt][nt][1] * LO_INV + bv1;
            float v10 = acc[mt][nt][2] + accc[mt][nt][2] * LO_INV + bv0;
            float v11 = acc[mt][nt][3] + accc[mt][nt][3] * LO_INV + bv1;
            if (relu) {
                v00 = fmaxf(v00, 0.f); v01 = fmaxf(v01, 0.f);
                v10 = fmaxf(v10, 0.f); v11 = fmaxf(v11, 0.f);
            }
            if (mode == 3) {
                stage[col * 68 + r0] = v00; stage[(col + 1) * 68 + r0] = v01;
                stage[col * 68 + r1] = v10; stage[(col + 1) * 68 + r1] = v11;
            } else if (out_f32 != nullptr) {
                *reinterpret_cast<float2*>(out_f32 + ((size_t)b * Tout + t0 + r0) * OC + oc0 + col) =
                    make_float2(v00, v01);
                *reinterpret_cast<float2*>(out_f32 + ((size_t)b * Tout + t0 + r1) * OC + oc0 + col) =
                    make_float2(v10, v11);
            } else {
                int tr0 = (mode == 2) ? (2 * (t0 + r0) + pair) : (t0 + r0);
                int tr1 = (mode == 2) ? (2 * (t0 + r1) + pair) : (t0 + r1);
                size_t o0 = ((size_t)b * Tout + tr0) * OC + oc0 + col;
                size_t o1 = ((size_t)b * Tout + tr1) * OC + oc0 + col;
                __half h00 = __float2half_rn(v00), h01 = __float2half_rn(v01);
                __half h10 = __float2half_rn(v10), h11 = __float2half_rn(v11);
                *reinterpret_cast<__half2*>(out_hi + o0) = __halves2half2(h00, h01);
                *reinterpret_cast<__half2*>(out_lo + o0) =
                    __halves2half2(__float2half_rn((v00 - __half2float(h00)) * LO_SCALE),
                                   __float2half_rn((v01 - __half2float(h01)) * LO_SCALE));
                *reinterpret_cast<__half2*>(out_hi + o1) = __halves2half2(h10, h11);
                *reinterpret_cast<__half2*>(out_lo + o1) =
                    __halves2half2(__float2half_rn((v10 - __half2float(h10)) * LO_SCALE),
                                   __float2half_rn((v11 - __half2float(h11)) * LO_SCALE));
            }
        }
    }
    if (mode == 3) {
        __syncthreads();
        // stage[col(oc_local)][m] -> out[b][oc0+col][2*(t0+m)+pair], BM=64
        for (int q = 0; q < 32; q++) {
            int idx = q * 256 + tid;
            int r = idx >> 6, m = idx & 63;
            out_f32[((size_t)(b * 256 + oc0 + r)) * 32768 + 2 * (t0 + m) + pair] =
                stage[r * 68 + m];
        }
    }
}

// ---------------- VQ: exact fp32 nearest code, q -> hi/lo fp16 ----------------
__global__ void __launch_bounds__(128)
vq_kernel(const float* __restrict__ z, const float* __restrict__ cb,
          const float* __restrict__ cnh,
          __half* __restrict__ qh, __half* __restrict__ ql) {
    extern __shared__ float cbs[];   // [512*64] codebook + [512] cnh
    int tid = threadIdx.x;
    for (int i = tid; i < 512 * 64 / 4; i += 128)
        reinterpret_cast<float4*>(cbs)[i] = reinterpret_cast<const float4*>(cb)[i];
    float* cns = cbs + 512 * 64;
    for (int i = tid; i < 512; i += 128) cns[i] = cnh[i];
    __syncthreads();

    int tg = blockIdx.x * 128 + tid;
    const float* zp = z + (size_t)tg * 64;
    float zr[64];
#pragma unroll
    for (int k = 0; k < 64; k++) zr[k] = zp[k];
    float best = -1e30f;
    int bi = 0;
    for (int c = 0; c < 512; c++) {
        const float* cr = cbs + c * 64;
        float dot = 0.f;
#pragma unroll
        for (int k = 0; k < 64; k++) dot = fmaf(zr[k], cr[k], dot);
        float s = dot - cns[c];
        if (s > best) { best = s; bi = c; }
    }
    const float* cw = cbs + bi * 64;
    __half2* oh = reinterpret_cast<__half2*>(qh + (size_t)tg * 64);
    __half2* ol = reinterpret_cast<__half2*>(ql + (size_t)tg * 64);
#pragma unroll
    for (int k = 0; k < 32; k++) {
        float a0 = cw[2 * k], a1 = cw[2 * k + 1];
        __half h0v = __float2half_rn(a0);
        __half h1v = __float2half_rn(a1);
        oh[k] = __halves2half2(h0v, h1v);
        ol[k] = __halves2half2(__float2half_rn((a0 - __half2float(h0v)) * LO_SCALE),
                               __float2half_rn((a1 - __half2float(h1v)) * LO_SCALE));
    }
}

// ---------------- launcher ----------------
extern "C" void kernel_launch(void* const* d_in, const int* in_sizes, int n_in,
                              void* d_out, int out_size) {
    (void)in_sizes; (void)n_in; (void)out_size;
    const float* inputs    = (const float*)d_in[0];
    const float* enc_w_in  = (const float*)d_in[1];
    const float* enc_b_in  = (const float*)d_in[2];
    const float* enc_ws    = (const float*)d_in[3];
    const float* enc_bs    = (const float*)d_in[4];
    const float* enc_w_out = (const float*)d_in[5];
    const float* enc_b_out = (const float*)d_in[6];
    const float* codebook  = (const float*)d_in[7];
    const float* dec_w_in  = (const float*)d_in[8];
    const float* dec_b_in  = (const float*)d_in[9];
    const float* dec_ws    = (const float*)d_in[10];
    const float* dec_bs    = (const float*)d_in[11];
    const float* dec_w_out = (const float*)d_in[12];
    const float* dec_b_out = (const float*)d_in[13];
    float* out = (float*)d_out;

    __half *h0, *l0, *h1, *l1, *qh, *ql, *wh, *wl;
    float *zT, *cnh;
    cudaGetSymbolAddress((void**)&h0, g_h0);
    cudaGetSymbolAddress((void**)&l0, g_l0);
    cudaGetSymbolAddress((void**)&h1, g_h1);
    cudaGetSymbolAddress((void**)&l1, g_l1);
    cudaGetSymbolAddress((void**)&zT, g_zT);
    cudaGetSymbolAddress((void**)&qh, g_qh);
    cudaGetSymbolAddress((void**)&ql, g_ql);
    cudaGetSymbolAddress((void**)&wh, g_whi);
    cudaGetSymbolAddress((void**)&wl, g_wlo);
    cudaGetSymbolAddress((void**)&cnh, g_cnh);

    const int GEMM_SMEM = 2 * 49152 + 1024;   // 2 stages of 48KB + align
    const int VQ_SMEM = 512 * 64 * 4 + 512 * 4;
    cudaFuncSetAttribute(conv_mma_kernel<64, 128>, cudaFuncAttributeMaxDynamicSharedMemorySize, GEMM_SMEM);
    cudaFuncSetAttribute(conv_mma_kernel<128, 64>, cudaFuncAttributeMaxDynamicSharedMemorySize, GEMM_SMEM);
    cudaFuncSetAttribute(vq_kernel, cudaFuncAttributeMaxDynamicSharedMemorySize, VQ_SMEM);

    const int WSLOT = 196608;

    // 0: all weight repacks in one launch
    repack_all_kernel<<<dim3(768, 9), 256>>>(enc_ws, enc_w_out, dec_w_in, dec_ws, dec_w_out, wh, wl);
    // 1
    cb_prep_kernel<<<1, 512>>>(codebook, cnh);
    // 2
    e1_kernel<<<dim3(256, 16), 256>>>(inputs, enc_w_in, enc_b_in, h0, l0);
    // 3..5: heavy convs — ncu -s 5 -c 1 lands inside the conv sequence
    conv_mma_kernel<64, 128><<<dim3(2, 128, 16), 256, GEMM_SMEM>>>(h0, l0, wh + 0 * WSLOT, wl + 0 * WSLOT,
        enc_bs + 0, h1, l1, nullptr, 256, 256, 16384, 8192, 1, 1);
    conv_mma_kernel<64, 128><<<dim3(2, 64, 16), 256, GEMM_SMEM>>>(h1, l1, wh + 1 * WSLOT, wl + 1 * WSLOT,
        enc_bs + 256, h0, l0, nullptr, 256, 256, 8192, 4096, 1, 1);
    conv_mma_kernel<64, 128><<<dim3(2, 32, 16), 256, GEMM_SMEM>>>(h0, l0, wh + 2 * WSLOT, wl + 2 * WSLOT,
        enc_bs + 512, h1, l1, nullptr, 256, 256, 4096, 2048, 1, 1);
    // 6
    conv_mma_kernel<128, 64><<<dim3(1, 16, 16), 256, GEMM_SMEM>>>(h1, l1, wh + 3 * WSLOT, wl + 3 * WSLOT,
        enc_b_out, nullptr, nullptr, zT, 256, 64, 2048, 2048, 0, 0);
    // 7
    vq_kernel<<<256, 128, VQ_SMEM>>>(zT, codebook, cnh, qh, ql);
    // 8..12: decoder
    conv_mma_kernel<64, 128><<<dim3(2, 32, 16), 256, GEMM_SMEM>>>(qh, ql, wh + 4 * WSLOT, wl + 4 * WSLOT,
        dec_b_in, h0, l0, nullptr, 64, 256, 2048, 2048, 0, 1);
    conv_mma_kernel<64, 128><<<dim3(4, 32, 16), 256, GEMM_SMEM>>>(h0, l0, wh + 5 * WSLOT, wl + 5 * WSLOT,
        dec_bs + 0, h1, l1, nullptr, 256, 256, 2048, 4096, 2, 1);
    conv_mma_kernel<64, 128><<<dim3(4, 64, 16), 256, GEMM_SMEM>>>(h1, l1, wh + 6 * WSLOT, wl + 6 * WSLOT,
        dec_bs + 256, h0, l0, nullptr, 256, 256, 4096, 8192, 2, 1);
    conv_mma_kernel<64, 128><<<dim3(4, 128, 16), 256, GEMM_SMEM>>>(h0, l0, wh + 7 * WSLOT, wl + 7 * WSLOT,
        dec_bs + 512, h1, l1, nullptr, 256, 256, 8192, 16384, 2, 1);
    conv_mma_kernel<64, 128><<<dim3(4, 256, 16), 256, GEMM_SMEM>>>(h1, l1, wh + 8 * WSLOT, wl + 8 * WSLOT,
        dec_b_out, nullptr, nullptr, out, 256, 256, 16384, 32768, 3, 0);
}

// round 15
// speedup vs baseline: 1.2775x; 1.1513x over previous
#include <cuda_runtime.h>
#include <cuda_fp16.h>

typedef unsigned long long u64;
typedef unsigned int u32;
#define DI __device__ __forceinline__

#define LO_SCALE 2048.f
#define LO_INV (1.f / 2048.f)

// ---------------- static scratch ----------------
__device__ __half g_h0[16*16384*256];
__device__ __half g_l0[16*16384*256];
__device__ __half g_h1[16*16384*256];
__device__ __half g_l1[16*16384*256];
__device__ float  g_zT[16*2048*64];
__device__ __half g_qh[16*2048*64];
__device__ __half g_ql[16*2048*64];
__device__ __half g_whi[9*196608];
__device__ __half g_wlo[9*196608];
__device__ float  g_cnh[512];

// ---------------- PTX helpers ----------------
DI u32 smem_u32(const void* p) {
    u32 a;
    asm("{ .reg .u64 t; cvta.to.shared.u64 t, %1; cvt.u32.u64 %0, t; }" : "=r"(a) : "l"(p));
    return a;
}
DI void cpa16(u32 dst, const void* src, int src_sz) {
    asm volatile("cp.async.cg.shared.global [%0], [%1], 16, %2;"
                 :: "r"(dst), "l"(src), "r"(src_sz) : "memory");
}
DI void cpa_commit() { asm volatile("cp.async.commit_group;" ::: "memory"); }
DI void cpa_wait1() { asm volatile("cp.async.wait_group 1;" ::: "memory"); }
DI void cpa_wait0() { asm volatile("cp.async.wait_group 0;" ::: "memory"); }
DI void ldsm4(u32* r, u32 addr) {
    asm volatile("ldmatrix.sync.aligned.m8n8.x4.shared.b16 {%0,%1,%2,%3}, [%4];"
                 : "=r"(r[0]), "=r"(r[1]), "=r"(r[2]), "=r"(r[3]) : "r"(addr));
}
DI void mma16816(float* c, const u32* a, u32 b0, u32 b1) {
    asm volatile(
        "mma.sync.aligned.m16n8k16.row.col.f32.f16.f16.f32 "
        "{%0,%1,%2,%3}, {%4,%5,%6,%7}, {%8,%9}, {%0,%1,%2,%3};"
        : "+f"(c[0]), "+f"(c[1]), "+f"(c[2]), "+f"(c[3])
        : "r"(a[0]), "r"(a[1]), "r"(a[2]), "r"(a[3]), "r"(b0), "r"(b1));
}
DI u32 swz(u32 o) { return o ^ ((o >> 3) & 0x70); }

// ---------------- single merged weight repack: all 9 slots ----------------
__global__ void repack_all_kernel(const float* __restrict__ enc_ws,
                                  const float* __restrict__ enc_w_out,
                                  const float* __restrict__ dec_w_in,
                                  const float* __restrict__ dec_ws,
                                  const float* __restrict__ dec_w_out,
                                  __half* __restrict__ wh, __half* __restrict__ wl) {
    const int WSLOT = 196608;
    int slot = blockIdx.y;
    const float* src;
    int OC, IC;
    if (slot < 3)       { src = enc_ws + slot * 196608;       OC = 256; IC = 256; }
    else if (slot == 3) { src = enc_w_out;                    OC = 64;  IC = 256; }
    else if (slot == 4) { src = dec_w_in;                     OC = 256; IC = 64;  }
    else if (slot < 8)  { src = dec_ws + (slot - 5) * 196608; OC = 256; IC = 256; }
    else                { src = dec_w_out;                    OC = 256; IC = 256; }

    int i = blockIdx.x * 256 + threadIdx.x;
    int n = OC * IC * 3;
    if (i >= n) return;
    int oc = i / (IC * 3);
    int r = i - oc * IC * 3;
    int ic = r / 3, k = r - ic * 3;
    int nch = IC >> 6, c = ic >> 6, j = ic & 63;
    float v = src[i];
    __half h = __float2half_rn(v);
    size_t d = (size_t)slot * WSLOT + ((size_t)(k * nch + c) * OC + oc) * 64 + j;
    wh[d] = h;
    wl[d] = __float2half_rn((v - __half2float(h)) * LO_SCALE);
}

__global__ void cb_prep_kernel(const float* __restrict__ cb, float* __restrict__ cnh) {
    int c = threadIdx.x;
    float s = 0.f;
    for (int k = 0; k < 64; k++) { float v = cb[c * 64 + k]; s += v * v; }
    cnh[c] = 0.5f * s;
}

// ---------------- encoder layer 1: IC=1, stride 2, relu, t-major hi/lo out ----------------
__global__ void e1_kernel(const float* __restrict__ x, const float* __restrict__ w,
                          const float* __restrict__ bias,
                          __half* __restrict__ oh, __half* __restrict__ ol) {
    __shared__ float xs[132];
    int b = blockIdx.y, tc = blockIdx.x * 64, tid = threadIdx.x;
    const float* xr = x + (size_t)b * 32768;
    for (int i = tid; i < 130; i += 256) {
        int pos = 2 * tc - 1 + i;
        xs[i] = (pos >= 0 && pos < 32768) ? xr[pos] : 0.f;
    }
    __syncthreads();
    float w0 = w[tid * 3], w1 = w[tid * 3 + 1], w2 = w[tid * 3 + 2], bv = bias[tid];
    for (int j = 0; j < 64; j++) {
        float v = fmaxf(bv + w0 * xs[2 * j] + w1 * xs[2 * j + 1] + w2 * xs[2 * j + 2], 0.f);
        __half h = __float2half_rn(v);
        size_t o = ((size_t)b * 16384 + tc + j) * 256 + tid;
        oh[o] = h;
        ol[o] = __float2half_rn((v - __half2float(h)) * LO_SCALE);
    }
}

// ---------------- generic mma.sync conv GEMM (fp16-split, scaled residuals) ----------------
// mode: 0=s1 conv, 1=s2 conv, 2=convT (pair-split), 3=convT final (fp32 ch-major out)
// nph:  3 = full split correction, 1 = hi-only (final layer; error ~4e-4 direct to output)
// grid: x = oc-tile (+pair for mode>=2), y = t-tile (BM rows), z = batch
template <int BM, int BN>
__global__ void __launch_bounds__(256, 2)
conv_mma_kernel(const __half* __restrict__ in_hi, const __half* __restrict__ in_lo,
                const __half* __restrict__ w_hi, const __half* __restrict__ w_lo,
                const float* __restrict__ bias,
                __half* __restrict__ out_hi, __half* __restrict__ out_lo,
                float* __restrict__ out_f32,
                int IC, int OC, int Tin, int Tout, int mode, int relu, int nph) {
    const int WN = BN / 32;
    const int ASZ = BM * 128;
    const int BSZ = BN * 128;
    const int STAGE = 2 * (ASZ + BSZ);   // 48KB

    extern __shared__ char smraw[];
    u32 sb0 = smem_u32(smraw);
    u32 sb = (sb0 + 1023) & ~1023u;
    char* smp = smraw + (sb - sb0);

    const int tid = threadIdx.x, lane = tid & 31, wid = tid >> 5;
    const int t0 = blockIdx.y * BM;
    int xb = blockIdx.x;
    int oc0, pair;
    if (mode >= 2) { oc0 = (xb & 1) * 128; pair = xb >> 1; }
    else           { oc0 = xb * BN; pair = 0; }
    const int b = blockIdx.z;
    const int nch = IC >> 6;
    const int nsub = (mode < 2) ? 3 * nch : (pair ? 2 * nch : nch);
    const size_t inb = (size_t)b * Tin * IC;

    const int wm = wid / WN, wn = wid % WN;
    const int mbase = wm * 32;

    float acc[2][4][4];     // hi*hi
    float accc[2][4][4];    // cross terms (scaled by LO_SCALE)
#pragma unroll
    for (int mt = 0; mt < 2; mt++)
#pragma unroll
        for (int nt = 0; nt < 4; nt++)
#pragma unroll
            for (int k = 0; k < 4; k++) { acc[mt][nt][k] = 0.f; accc[mt][nt][k] = 0.f; }

    auto geo = [&](int i, int& c, int& kap, int& del) {
        if (mode < 2) { c = i / 3; int s = i - 3 * c; kap = s; del = s - 1; }
        else if (!pair) { c = i; kap = 1; del = 0; }
        else { c = i >> 1; if (i & 1) { kap = 2; del = 1; } else { kap = 0; del = 0; } }
    };
    // stage p: A_hi @0, A_lo @ASZ, B_hi @2*ASZ, B_lo @2*ASZ+BSZ
    auto load_chunk = [&](int i, int p) {
        int c, kap, del;
        geo(i, c, kap, del);
        u32 abase = sb + p * STAGE;
        u32 bbase = abase + 2 * ASZ;
        int r0 = tid >> 3, qd = tid & 7;
        const __half* sH = in_hi + inb + c * 64 + qd * 8;
        const __half* sL = in_lo + inb + c * 64 + qd * 8;
#pragma unroll
        for (int it = 0; it < BM / 32; it++) {
            int r = r0 + it * 32;
            int g = (mode == 1) ? (2 * (t0 + r) + del) : (t0 + r + del);
            int ok = (g >= 0 && g < Tin) ? 16 : 0;
            int gc = ok ? g : 0;
            u32 so = swz((u32)(r * 128 + qd * 16));
            cpa16(abase + so, sH + (size_t)gc * IC, ok);
            if (nph == 3) cpa16(abase + ASZ + so, sL + (size_t)gc * IC, ok);
        }
        const __half* wH = w_hi + ((size_t)(kap * nch + c) * OC + oc0) * 64 + qd * 8;
        const __half* wL = w_lo + ((size_t)(kap * nch + c) * OC + oc0) * 64 + qd * 8;
#pragma unroll
        for (int it = 0; it < BN / 32; it++) {
            int r = r0 + it * 32;
            u32 so = swz((u32)(r * 128 + qd * 16));
            cpa16(bbase + so, wH + (size_t)r * 64, 16);
            if (nph == 3) cpa16(bbase + BSZ + so, wL + (size_t)r * 64, 16);
        }
    };

    load_chunk(0, 0);
    cpa_commit();
    if (nsub > 1) { load_chunk(1, 1); cpa_commit(); }

    for (int i = 0; i < nsub; i++) {
        int p = i & 1;
        if (i + 1 < nsub) cpa_wait1(); else cpa_wait0();
        __syncthreads();

        u32 abase = sb + p * STAGE;
        u32 bbase = abase + 2 * ASZ;
#pragma unroll
        for (int ks = 0; ks < 4; ks++) {
            int arow = mbase + (lane & 15);
            int akb = ks * 32 + (lane >> 4) * 16;
            u32 aad0 = abase + swz((u32)(arow * 128 + akb));
            u32 aad1 = abase + swz((u32)((arow + 16) * 128 + akb));

            u32 ah[2][4], bh[8];
            ldsm4(ah[0], aad0);
            ldsm4(ah[1], aad1);
            u32 badr[2];
#pragma unroll
            for (int q = 0; q < 2; q++) {
                int brow = wn * 32 + q * 16 + ((lane >> 4) & 1) * 8 + (lane & 7);
                int bkb = ks * 32 + ((lane >> 3) & 1) * 16;
                badr[q] = bbase + swz((u32)(brow * 128 + bkb));
                ldsm4(&bh[q * 4], badr[q]);
            }
            // Phase 1: hh -> acc
#pragma unroll
            for (int mt = 0; mt < 2; mt++)
#pragma unroll
                for (int nt = 0; nt < 4; nt++) {
                    int bi = (nt >> 1) * 4 + (nt & 1) * 2;
                    mma16816(acc[mt][nt], ah[mt], bh[bi], bh[bi + 1]);
                }
            if (nph == 3) {
                u32 al[2][4], bl[8];
                ldsm4(al[0], aad0 + ASZ);
                ldsm4(al[1], aad1 + ASZ);
                ldsm4(&bl[0], badr[0] + BSZ);
                ldsm4(&bl[4], badr[1] + BSZ);
                // Phase 2: A-hi x B-lo
#pragma unroll
                for (int mt = 0; mt < 2; mt++)
#pragma unroll
                    for (int nt = 0; nt < 4; nt++) {
                        int bi = (nt >> 1) * 4 + (nt & 1) * 2;
                        mma16816(accc[mt][nt], ah[mt], bl[bi], bl[bi + 1]);
                    }
                // Phase 3: A-lo x B-hi
#pragma unroll
                for (int mt = 0; mt < 2; mt++)
#pragma unroll
                    for (int nt = 0; nt < 4; nt++) {
                        int bi = (nt >> 1) * 4 + (nt & 1) * 2;
                        mma16816(accc[mt][nt], al[mt], bh[bi], bh[bi + 1]);
                    }
            }
        }
        __syncthreads();
        if (i + 2 < nsub) { load_chunk(i + 2, p); cpa_commit(); }
    }

    // ---------------- epilogue ----------------
    int g = lane >> 2, tg = lane & 3;
    float* stage = reinterpret_cast<float*>(smp);   // mode 3 staging [col][68]
    float corr = (nph == 3) ? LO_INV : 0.f;
#pragma unroll
    for (int mt = 0; mt < 2; mt++) {
#pragma unroll
        for (int nt = 0; nt < 4; nt++) {
            int col = wn * 32 + nt * 8 + tg * 2;
            float bv0 = __ldg(bias + oc0 + col);
            float bv1 = __ldg(bias + oc0 + col + 1);
            int r0 = mbase + mt * 16 + g, r1 = r0 + 8;
            float v00 = acc[mt][nt][0] + accc[mt][nt][0] * corr + bv0;
            float v01 = acc[mt][nt][1] + accc[mt][nt][1] * corr + bv1;
            float v10 = acc[mt][nt][2] + accc[mt][nt][2] * corr + bv0;
            float v11 = acc[mt][nt][3] + accc[mt][nt][3] * corr + bv1;
            if (relu) {
                v00 = fmaxf(v00, 0.f); v01 = fmaxf(v01, 0.f);
                v10 = fmaxf(v10, 0.f); v11 = fmaxf(v11, 0.f);
            }
            if (mode == 3) {
                stage[col * 68 + r0] = v00; stage[(col + 1) * 68 + r0] = v01;
                stage[col * 68 + r1] = v10; stage[(col + 1) * 68 + r1] = v11;
            } else if (out_f32 != nullptr) {
                *reinterpret_cast<float2*>(out_f32 + ((size_t)b * Tout + t0 + r0) * OC + oc0 + col) =
                    make_float2(v00, v01);
                *reinterpret_cast<float2*>(out_f32 + ((size_t)b * Tout + t0 + r1) * OC + oc0 + col) =
                    make_float2(v10, v11);
            } else {
                int tr0 = (mode == 2) ? (2 * (t0 + r0) + pair) : (t0 + r0);
                int tr1 = (mode == 2) ? (2 * (t0 + r1) + pair) : (t0 + r1);
                size_t o0 = ((size_t)b * Tout + tr0) * OC + oc0 + col;
                size_t o1 = ((size_t)b * Tout + tr1) * OC + oc0 + col;
                __half h00 = __float2half_rn(v00), h01 = __float2half_rn(v01);
                __half h10 = __float2half_rn(v10), h11 = __float2half_rn(v11);
                *reinterpret_cast<__half2*>(out_hi + o0) = __halves2half2(h00, h01);
                *reinterpret_cast<__half2*>(out_lo + o0) =
                    __halves2half2(__float2half_rn((v00 - __half2float(h00)) * LO_SCALE),
                                   __float2half_rn((v01 - __half2float(h01)) * LO_SCALE));
                *reinterpret_cast<__half2*>(out_hi + o1) = __halves2half2(h10, h11);
                *reinterpret_cast<__half2*>(out_lo + o1) =
                    __halves2half2(__float2half_rn((v10 - __half2float(h10)) * LO_SCALE),
                                   __float2half_rn((v11 - __half2float(h11)) * LO_SCALE));
            }
        }
    }
    if (mode == 3) {
        __syncthreads();
        for (int q = 0; q < 32; q++) {
            int idx = q * 256 + tid;
            int r = idx >> 6, m = idx & 63;
            out_f32[((size_t)(b * 256 + oc0 + r)) * 32768 + 2 * (t0 + m) + pair] =
                stage[r * 68 + m];
        }
    }
}

// ---------------- VQ: exact fp32 nearest code, q -> hi/lo fp16 ----------------
__global__ void __launch_bounds__(128)
vq_kernel(const float* __restrict__ z, const float* __restrict__ cb,
          const float* __restrict__ cnh,
          __half* __restrict__ qh, __half* __restrict__ ql) {
    extern __shared__ float cbs[];
    int tid = threadIdx.x;
    for (int i = tid; i < 512 * 64 / 4; i += 128)
        reinterpret_cast<float4*>(cbs)[i] = reinterpret_cast<const float4*>(cb)[i];
    float* cns = cbs + 512 * 64;
    for (int i = tid; i < 512; i += 128) cns[i] = cnh[i];
    __syncthreads();

    int tg = blockIdx.x * 128 + tid;
    const float* zp = z + (size_t)tg * 64;
    float zr[64];
#pragma unroll
    for (int k = 0; k < 64; k++) zr[k] = zp[k];
    float best = -1e30f;
    int bi = 0;
    for (int c = 0; c < 512; c++) {
        const float* cr = cbs + c * 64;
        float dot = 0.f;
#pragma unroll
        for (int k = 0; k < 64; k++) dot = fmaf(zr[k], cr[k], dot);
        float s = dot - cns[c];
        if (s > best) { best = s; bi = c; }
    }
    const float* cw = cbs + bi * 64;
    __half2* oh = reinterpret_cast<__half2*>(qh + (size_t)tg * 64);
    __half2* ol = reinterpret_cast<__half2*>(ql + (size_t)tg * 64);
#pragma unroll
    for (int k = 0; k < 32; k++) {
        float a0 = cw[2 * k], a1 = cw[2 * k + 1];
        __half h0v = __float2half_rn(a0);
        __half h1v = __float2half_rn(a1);
        oh[k] = __halves2half2(h0v, h1v);
        ol[k] = __halves2half2(__float2half_rn((a0 - __half2float(h0v)) * LO_SCALE),
                               __float2half_rn((a1 - __half2float(h1v)) * LO_SCALE));
    }
}

// ---------------- launcher ----------------
extern "C" void kernel_launch(void* const* d_in, const int* in_sizes, int n_in,
                              void* d_out, int out_size) {
    (void)in_sizes; (void)n_in; (void)out_size;
    const float* inputs    = (const float*)d_in[0];
    const float* enc_w_in  = (const float*)d_in[1];
    const float* enc_b_in  = (const float*)d_in[2];
    const float* enc_ws    = (const float*)d_in[3];
    const float* enc_bs    = (const float*)d_in[4];
    const float* enc_w_out = (const float*)d_in[5];
    const float* enc_b_out = (const float*)d_in[6];
    const float* codebook  = (const float*)d_in[7];
    const float* dec_w_in  = (const float*)d_in[8];
    const float* dec_b_in  = (const float*)d_in[9];
    const float* dec_ws    = (const float*)d_in[10];
    const float* dec_bs    = (const float*)d_in[11];
    const float* dec_w_out = (const float*)d_in[12];
    const float* dec_b_out = (const float*)d_in[13];
    float* out = (float*)d_out;

    __half *h0, *l0, *h1, *l1, *qh, *ql, *wh, *wl;
    float *zT, *cnh;
    cudaGetSymbolAddress((void**)&h0, g_h0);
    cudaGetSymbolAddress((void**)&l0, g_l0);
    cudaGetSymbolAddress((void**)&h1, g_h1);
    cudaGetSymbolAddress((void**)&l1, g_l1);
    cudaGetSymbolAddress((void**)&zT, g_zT);
    cudaGetSymbolAddress((void**)&qh, g_qh);
    cudaGetSymbolAddress((void**)&ql, g_ql);
    cudaGetSymbolAddress((void**)&wh, g_whi);
    cudaGetSymbolAddress((void**)&wl, g_wlo);
    cudaGetSymbolAddress((void**)&cnh, g_cnh);

    const int GEMM_SMEM = 2 * 49152 + 1024;
    const int VQ_SMEM = 512 * 64 * 4 + 512 * 4;
    cudaFuncSetAttribute(conv_mma_kernel<64, 128>, cudaFuncAttributeMaxDynamicSharedMemorySize, GEMM_SMEM);
    cudaFuncSetAttribute(conv_mma_kernel<128, 64>, cudaFuncAttributeMaxDynamicSharedMemorySize, GEMM_SMEM);
    cudaFuncSetAttribute(vq_kernel, cudaFuncAttributeMaxDynamicSharedMemorySize, VQ_SMEM);

    const int WSLOT = 196608;

    repack_all_kernel<<<dim3(768, 9), 256>>>(enc_ws, enc_w_out, dec_w_in, dec_ws, dec_w_out, wh, wl);
    cb_prep_kernel<<<1, 512>>>(codebook, cnh);
    e1_kernel<<<dim3(256, 16), 256>>>(inputs, enc_w_in, enc_b_in, h0, l0);
    // heavy convs at launch indices 3..5 for ncu
    conv_mma_kernel<64, 128><<<dim3(2, 128, 16), 256, GEMM_SMEM>>>(h0, l0, wh + 0 * WSLOT, wl + 0 * WSLOT,
        enc_bs + 0, h1, l1, nullptr, 256, 256, 16384, 8192, 1, 1, 3);
    conv_mma_kernel<64, 128><<<dim3(2, 64, 16), 256, GEMM_SMEM>>>(h1, l1, wh + 1 * WSLOT, wl + 1 * WSLOT,
        enc_bs + 256, h0, l0, nullptr, 256, 256, 8192, 4096, 1, 1, 3);
    conv_mma_kernel<64, 128><<<dim3(2, 32, 16), 256, GEMM_SMEM>>>(h0, l0, wh + 2 * WSLOT, wl + 2 * WSLOT,
        enc_bs + 512, h1, l1, nullptr, 256, 256, 4096, 2048, 1, 1, 3);
    conv_mma_kernel<128, 64><<<dim3(1, 16, 16), 256, GEMM_SMEM>>>(h1, l1, wh + 3 * WSLOT, wl + 3 * WSLOT,
        enc_b_out, nullptr, nullptr, zT, 256, 64, 2048, 2048, 0, 0, 3);
    vq_kernel<<<256, 128, VQ_SMEM>>>(zT, codebook, cnh, qh, ql);
    conv_mma_kernel<64, 128><<<dim3(2, 32, 16), 256, GEMM_SMEM>>>(qh, ql, wh + 4 * WSLOT, wl + 4 * WSLOT,
        dec_b_in, h0, l0, nullptr, 64, 256, 2048, 2048, 0, 1, 3);
    conv_mma_kernel<64, 128><<<dim3(4, 32, 16), 256, GEMM_SMEM>>>(h0, l0, wh + 5 * WSLOT, wl + 5 * WSLOT,
        dec_bs + 0, h1, l1, nullptr, 256, 256, 2048, 4096, 2, 1, 3);
    conv_mma_kernel<64, 128><<<dim3(4, 64, 16), 256, GEMM_SMEM>>>(h1, l1, wh + 6 * WSLOT, wl + 6 * WSLOT,
        dec_bs + 256, h0, l0, nullptr, 256, 256, 4096, 8192, 2, 1, 3);
    conv_mma_kernel<64, 128><<<dim3(4, 128, 16), 256, GEMM_SMEM>>>(h0, l0, wh + 7 * WSLOT, wl + 7 * WSLOT,
        dec_bs + 512, h1, l1, nullptr, 256, 256, 8192, 16384, 2, 1, 3);
    // final layer: hi-only (1 phase) — error ~4e-4 rel, lands directly in output
    conv_mma_kernel<64, 128><<<dim3(4, 256, 16), 256, GEMM_SMEM>>>(h1, l1, wh + 8 * WSLOT, wl + 8 * WSLOT,
        dec_b_out, nullptr, nullptr, out, 256, 256, 16384, 32768, 3, 0, 1);
}

// round 16
// speedup vs baseline: 1.3537x; 1.0597x over previous
#include <cuda_runtime.h>
#include <cuda_fp16.h>

typedef unsigned long long u64;
typedef unsigned int u32;
#define DI __device__ __forceinline__

#define LO_SCALE 2048.f
#define LO_INV (1.f / 2048.f)

// ---------------- static scratch ----------------
__device__ __half g_h0[16*16384*256];
__device__ __half g_l0[16*16384*256];
__device__ __half g_h1[16*16384*256];
__device__ __half g_l1[16*16384*256];
__device__ float  g_zT[16*2048*64];
__device__ __half g_qh[16*2048*64];
__device__ __half g_ql[16*2048*64];
__device__ __half g_whi[9*196608];
__device__ __half g_wlo[9*196608];
__device__ float  g_cnh[512];

// ---------------- PTX helpers ----------------
DI u32 smem_u32(const void* p) {
    u32 a;
    asm("{ .reg .u64 t; cvta.to.shared.u64 t, %1; cvt.u32.u64 %0, t; }" : "=r"(a) : "l"(p));
    return a;
}
DI void cpa16(u32 dst, const void* src, int src_sz) {
    asm volatile("cp.async.cg.shared.global [%0], [%1], 16, %2;"
                 :: "r"(dst), "l"(src), "r"(src_sz) : "memory");
}
DI void cpa_commit() { asm volatile("cp.async.commit_group;" ::: "memory"); }
DI void cpa_wait1() { asm volatile("cp.async.wait_group 1;" ::: "memory"); }
DI void cpa_wait0() { asm volatile("cp.async.wait_group 0;" ::: "memory"); }
DI void ldsm4(u32* r, u32 addr) {
    asm volatile("ldmatrix.sync.aligned.m8n8.x4.shared.b16 {%0,%1,%2,%3}, [%4];"
                 : "=r"(r[0]), "=r"(r[1]), "=r"(r[2]), "=r"(r[3]) : "r"(addr));
}
DI void mma16816(float* c, const u32* a, u32 b0, u32 b1) {
    asm volatile(
        "mma.sync.aligned.m16n8k16.row.col.f32.f16.f16.f32 "
        "{%0,%1,%2,%3}, {%4,%5,%6,%7}, {%8,%9}, {%0,%1,%2,%3};"
        : "+f"(c[0]), "+f"(c[1]), "+f"(c[2]), "+f"(c[3])
        : "r"(a[0]), "r"(a[1]), "r"(a[2]), "r"(a[3]), "r"(b0), "r"(b1));
}
DI u32 swz(u32 o) { return o ^ ((o >> 3) & 0x70); }

// ---------------- single merged weight repack: all 9 slots ----------------
__global__ void repack_all_kernel(const float* __restrict__ enc_ws,
                                  const float* __restrict__ enc_w_out,
                                  const float* __restrict__ dec_w_in,
                                  const float* __restrict__ dec_ws,
                                  const float* __restrict__ dec_w_out,
                                  __half* __restrict__ wh, __half* __restrict__ wl) {
    const int WSLOT = 196608;
    int slot = blockIdx.y;
    const float* src;
    int OC, IC;
    if (slot < 3)       { src = enc_ws + slot * 196608;       OC = 256; IC = 256; }
    else if (slot == 3) { src = enc_w_out;                    OC = 64;  IC = 256; }
    else if (slot == 4) { src = dec_w_in;                     OC = 256; IC = 64;  }
    else if (slot < 8)  { src = dec_ws + (slot - 5) * 196608; OC = 256; IC = 256; }
    else                { src = dec_w_out;                    OC = 256; IC = 256; }

    int i = blockIdx.x * 256 + threadIdx.x;
    int n = OC * IC * 3;
    if (i >= n) return;
    int oc = i / (IC * 3);
    int r = i - oc * IC * 3;
    int ic = r / 3, k = r - ic * 3;
    int nch = IC >> 6, c = ic >> 6, j = ic & 63;
    float v = src[i];
    __half h = __float2half_rn(v);
    size_t d = (size_t)slot * WSLOT + ((size_t)(k * nch + c) * OC + oc) * 64 + j;
    wh[d] = h;
    wl[d] = __float2half_rn((v - __half2float(h)) * LO_SCALE);
}

__global__ void cb_prep_kernel(const float* __restrict__ cb, float* __restrict__ cnh) {
    int c = threadIdx.x;
    float s = 0.f;
    for (int k = 0; k < 64; k++) { float v = cb[c * 64 + k]; s += v * v; }
    cnh[c] = 0.5f * s;
}

// ---------------- encoder layer 1: IC=1, stride 2, relu, t-major hi/lo out ----------------
__global__ void e1_kernel(const float* __restrict__ x, const float* __restrict__ w,
                          const float* __restrict__ bias,
                          __half* __restrict__ oh, __half* __restrict__ ol) {
    __shared__ float xs[132];
    int b = blockIdx.y, tc = blockIdx.x * 64, tid = threadIdx.x;
    const float* xr = x + (size_t)b * 32768;
    for (int i = tid; i < 130; i += 256) {
        int pos = 2 * tc - 1 + i;
        xs[i] = (pos >= 0 && pos < 32768) ? xr[pos] : 0.f;
    }
    __syncthreads();
    float w0 = w[tid * 3], w1 = w[tid * 3 + 1], w2 = w[tid * 3 + 2], bv = bias[tid];
    for (int j = 0; j < 64; j++) {
        float v = fmaxf(bv + w0 * xs[2 * j] + w1 * xs[2 * j + 1] + w2 * xs[2 * j + 2], 0.f);
        __half h = __float2half_rn(v);
        size_t o = ((size_t)b * 16384 + tc + j) * 256 + tid;
        oh[o] = h;
        ol[o] = __float2half_rn((v - __half2float(h)) * LO_SCALE);
    }
}

// ---------------- generic mma.sync conv GEMM (fp16-split, scaled residuals) ----------------
// mode: 0=s1 conv, 1=s2 conv, 2=convT (pair-split), 3=convT final (fp32 ch-major out)
// nph:  3 = full split; 2 = phases 1+3 (drop weight-residual term, ~2e-4/layer);
//       1 = hi-only (final layer)
// grid: x = oc-tile (+pair for mode>=2), y = t-tile (BM rows), z = batch
template <int BM, int BN>
__global__ void __launch_bounds__(256, 2)
conv_mma_kernel(const __half* __restrict__ in_hi, const __half* __restrict__ in_lo,
                const __half* __restrict__ w_hi, const __half* __restrict__ w_lo,
                const float* __restrict__ bias,
                __half* __restrict__ out_hi, __half* __restrict__ out_lo,
                float* __restrict__ out_f32,
                int IC, int OC, int Tin, int Tout, int mode, int relu, int nph) {
    const int WN = BN / 32;
    const int ASZ = BM * 128;
    const int BSZ = BN * 128;
    const int STAGE = 2 * (ASZ + BSZ);   // 48KB

    extern __shared__ char smraw[];
    u32 sb0 = smem_u32(smraw);
    u32 sb = (sb0 + 1023) & ~1023u;
    char* smp = smraw + (sb - sb0);

    const int tid = threadIdx.x, lane = tid & 31, wid = tid >> 5;
    const int t0 = blockIdx.y * BM;
    int xb = blockIdx.x;
    int oc0, pair;
    if (mode >= 2) { oc0 = (xb & 1) * 128; pair = xb >> 1; }
    else           { oc0 = xb * BN; pair = 0; }
    const int b = blockIdx.z;
    const int nch = IC >> 6;
    const int nsub = (mode < 2) ? 3 * nch : (pair ? 2 * nch : nch);
    const size_t inb = (size_t)b * Tin * IC;

    const int wm = wid / WN, wn = wid % WN;
    const int mbase = wm * 32;

    float acc[2][4][4];     // hi*hi
    float accc[2][4][4];    // cross terms (scaled by LO_SCALE)
#pragma unroll
    for (int mt = 0; mt < 2; mt++)
#pragma unroll
        for (int nt = 0; nt < 4; nt++)
#pragma unroll
            for (int k = 0; k < 4; k++) { acc[mt][nt][k] = 0.f; accc[mt][nt][k] = 0.f; }

    auto geo = [&](int i, int& c, int& kap, int& del) {
        if (mode < 2) { c = i / 3; int s = i - 3 * c; kap = s; del = s - 1; }
        else if (!pair) { c = i; kap = 1; del = 0; }
        else { c = i >> 1; if (i & 1) { kap = 2; del = 1; } else { kap = 0; del = 0; } }
    };
    // stage p: A_hi @0, A_lo @ASZ, B_hi @2*ASZ, B_lo @2*ASZ+BSZ
    auto load_chunk = [&](int i, int p) {
        int c, kap, del;
        geo(i, c, kap, del);
        u32 abase = sb + p * STAGE;
        u32 bbase = abase + 2 * ASZ;
        int r0 = tid >> 3, qd = tid & 7;
        const __half* sH = in_hi + inb + c * 64 + qd * 8;
        const __half* sL = in_lo + inb + c * 64 + qd * 8;
#pragma unroll
        for (int it = 0; it < BM / 32; it++) {
            int r = r0 + it * 32;
            int g = (mode == 1) ? (2 * (t0 + r) + del) : (t0 + r + del);
            int ok = (g >= 0 && g < Tin) ? 16 : 0;
            int gc = ok ? g : 0;
            u32 so = swz((u32)(r * 128 + qd * 16));
            cpa16(abase + so, sH + (size_t)gc * IC, ok);
            if (nph >= 2) cpa16(abase + ASZ + so, sL + (size_t)gc * IC, ok);
        }
        const __half* wH = w_hi + ((size_t)(kap * nch + c) * OC + oc0) * 64 + qd * 8;
        const __half* wL = w_lo + ((size_t)(kap * nch + c) * OC + oc0) * 64 + qd * 8;
#pragma unroll
        for (int it = 0; it < BN / 32; it++) {
            int r = r0 + it * 32;
            u32 so = swz((u32)(r * 128 + qd * 16));
            cpa16(bbase + so, wH + (size_t)r * 64, 16);
            if (nph == 3) cpa16(bbase + BSZ + so, wL + (size_t)r * 64, 16);
        }
    };

    load_chunk(0, 0);
    cpa_commit();
    if (nsub > 1) { load_chunk(1, 1); cpa_commit(); }

    for (int i = 0; i < nsub; i++) {
        int p = i & 1;
        if (i + 1 < nsub) cpa_wait1(); else cpa_wait0();
        __syncthreads();

        u32 abase = sb + p * STAGE;
        u32 bbase = abase + 2 * ASZ;
#pragma unroll
        for (int ks = 0; ks < 4; ks++) {
            int arow = mbase + (lane & 15);
            int akb = ks * 32 + (lane >> 4) * 16;
            u32 aad0 = abase + swz((u32)(arow * 128 + akb));
            u32 aad1 = abase + swz((u32)((arow + 16) * 128 + akb));

            u32 ah[2][4], bh[8];
            ldsm4(ah[0], aad0);
            ldsm4(ah[1], aad1);
            u32 badr[2];
#pragma unroll
            for (int q = 0; q < 2; q++) {
                int brow = wn * 32 + q * 16 + ((lane >> 4) & 1) * 8 + (lane & 7);
                int bkb = ks * 32 + ((lane >> 3) & 1) * 16;
                badr[q] = bbase + swz((u32)(brow * 128 + bkb));
                ldsm4(&bh[q * 4], badr[q]);
            }
            // Phase 1: hh -> acc
#pragma unroll
            for (int mt = 0; mt < 2; mt++)
#pragma unroll
                for (int nt = 0; nt < 4; nt++) {
                    int bi = (nt >> 1) * 4 + (nt & 1) * 2;
                    mma16816(acc[mt][nt], ah[mt], bh[bi], bh[bi + 1]);
                }
            if (nph == 3) {
                u32 bl[8];
                ldsm4(&bl[0], badr[0] + BSZ);
                ldsm4(&bl[4], badr[1] + BSZ);
                // Phase 2: A-hi x B-lo
#pragma unroll
                for (int mt = 0; mt < 2; mt++)
#pragma unroll
                    for (int nt = 0; nt < 4; nt++) {
                        int bi = (nt >> 1) * 4 + (nt & 1) * 2;
                        mma16816(accc[mt][nt], ah[mt], bl[bi], bl[bi + 1]);
                    }
            }
            if (nph >= 2) {
                u32 al[2][4];
                ldsm4(al[0], aad0 + ASZ);
                ldsm4(al[1], aad1 + ASZ);
                // Phase 3: A-lo x B-hi
#pragma unroll
                for (int mt = 0; mt < 2; mt++)
#pragma unroll
                    for (int nt = 0; nt < 4; nt++) {
                        int bi = (nt >> 1) * 4 + (nt & 1) * 2;
                        mma16816(accc[mt][nt], al[mt], bh[bi], bh[bi + 1]);
                    }
            }
        }
        __syncthreads();
        if (i + 2 < nsub) { load_chunk(i + 2, p); cpa_commit(); }
    }

    // ---------------- epilogue ----------------
    int g = lane >> 2, tg = lane & 3;
    float* stage = reinterpret_cast<float*>(smp);   // mode 3 staging [col][68]
    float corr = (nph >= 2) ? LO_INV : 0.f;
#pragma unroll
    for (int mt = 0; mt < 2; mt++) {
#pragma unroll
        for (int nt = 0; nt < 4; nt++) {
            int col = wn * 32 + nt * 8 + tg * 2;
            float bv0 = __ldg(bias + oc0 + col);
            float bv1 = __ldg(bias + oc0 + col + 1);
            int r0 = mbase + mt * 16 + g, r1 = r0 + 8;
            float v00 = acc[mt][nt][0] + accc[mt][nt][0] * corr + bv0;
            float v01 = acc[mt][nt][1] + accc[mt][nt][1] * corr + bv1;
            float v10 = acc[mt][nt][2] + accc[mt][nt][2] * corr + bv0;
            float v11 = acc[mt][nt][3] + accc[mt][nt][3] * corr + bv1;
            if (relu) {
                v00 = fmaxf(v00, 0.f); v01 = fmaxf(v01, 0.f);
                v10 = fmaxf(v10, 0.f); v11 = fmaxf(v11, 0.f);
            }
            if (mode == 3) {
                stage[col * 68 + r0] = v00; stage[(col + 1) * 68 + r0] = v01;
                stage[col * 68 + r1] = v10; stage[(col + 1) * 68 + r1] = v11;
            } else if (out_f32 != nullptr) {
                *reinterpret_cast<float2*>(out_f32 + ((size_t)b * Tout + t0 + r0) * OC + oc0 + col) =
                    make_float2(v00, v01);
                *reinterpret_cast<float2*>(out_f32 + ((size_t)b * Tout + t0 + r1) * OC + oc0 + col) =
                    make_float2(v10, v11);
            } else {
                int tr0 = (mode == 2) ? (2 * (t0 + r0) + pair) : (t0 + r0);
                int tr1 = (mode == 2) ? (2 * (t0 + r1) + pair) : (t0 + r1);
                size_t o0 = ((size_t)b * Tout + tr0) * OC + oc0 + col;
                size_t o1 = ((size_t)b * Tout + tr1) * OC + oc0 + col;
                __half h00 = __float2half_rn(v00), h01 = __float2half_rn(v01);
                __half h10 = __float2half_rn(v10), h11 = __float2half_rn(v11);
                *reinterpret_cast<__half2*>(out_hi + o0) = __halves2half2(h00, h01);
                *reinterpret_cast<__half2*>(out_lo + o0) =
                    __halves2half2(__float2half_rn((v00 - __half2float(h00)) * LO_SCALE),
                                   __float2half_rn((v01 - __half2float(h01)) * LO_SCALE));
                *reinterpret_cast<__half2*>(out_hi + o1) = __halves2half2(h10, h11);
                *reinterpret_cast<__half2*>(out_lo + o1) =
                    __halves2half2(__float2half_rn((v10 - __half2float(h10)) * LO_SCALE),
                                   __float2half_rn((v11 - __half2float(h11)) * LO_SCALE));
            }
        }
    }
    if (mode == 3) {
        __syncthreads();
        for (int q = 0; q < 32; q++) {
            int idx = q * 256 + tid;
            int r = idx >> 6, m = idx & 63;
            out_f32[((size_t)(b * 256 + oc0 + r)) * 32768 + 2 * (t0 + m) + pair] =
                stage[r * 68 + m];
        }
    }
}

// ---------------- VQ: exact fp32 nearest code, q -> hi/lo fp16 ----------------
__global__ void __launch_bounds__(128)
vq_kernel(const float* __restrict__ z, const float* __restrict__ cb,
          const float* __restrict__ cnh,
          __half* __restrict__ qh, __half* __restrict__ ql) {
    extern __shared__ float cbs[];
    int tid = threadIdx.x;
    for (int i = tid; i < 512 * 64 / 4; i += 128)
        reinterpret_cast<float4*>(cbs)[i] = reinterpret_cast<const float4*>(cb)[i];
    float* cns = cbs + 512 * 64;
    for (int i = tid; i < 512; i += 128) cns[i] = cnh[i];
    __syncthreads();

    int tg = blockIdx.x * 128 + tid;
    const float* zp = z + (size_t)tg * 64;
    float zr[64];
#pragma unroll
    for (int k = 0; k < 64; k++) zr[k] = zp[k];
    float best = -1e30f;
    int bi = 0;
    for (int c = 0; c < 512; c++) {
        const float* cr = cbs + c * 64;
        float dot = 0.f;
#pragma unroll
        for (int k = 0; k < 64; k++) dot = fmaf(zr[k], cr[k], dot);
        float s = dot - cns[c];
        if (s > best) { best = s; bi = c; }
    }
    const float* cw = cbs + bi * 64;
    __half2* oh = reinterpret_cast<__half2*>(qh + (size_t)tg * 64);
    __half2* ol = reinterpret_cast<__half2*>(ql + (size_t)tg * 64);
#pragma unroll
    for (int k = 0; k < 32; k++) {
        float a0 = cw[2 * k], a1 = cw[2 * k + 1];
        __half h0v = __float2half_rn(a0);
        __half h1v = __float2half_rn(a1);
        oh[k] = __halves2half2(h0v, h1v);
        ol[k] = __halves2half2(__float2half_rn((a0 - __half2float(h0v)) * LO_SCALE),
                               __float2half_rn((a1 - __half2float(h1v)) * LO_SCALE));
    }
}

// ---------------- launcher ----------------
extern "C" void kernel_launch(void* const* d_in, const int* in_sizes, int n_in,
                              void* d_out, int out_size) {
    (void)in_sizes; (void)n_in; (void)out_size;
    const float* inputs    = (const float*)d_in[0];
    const float* enc_w_in  = (const float*)d_in[1];
    const float* enc_b_in  = (const float*)d_in[2];
    const float* enc_ws    = (const float*)d_in[3];
    const float* enc_bs    = (const float*)d_in[4];
    const float* enc_w_out = (const float*)d_in[5];
    const float* enc_b_out = (const float*)d_in[6];
    const float* codebook  = (const float*)d_in[7];
    const float* dec_w_in  = (const float*)d_in[8];
    const float* dec_b_in  = (const float*)d_in[9];
    const float* dec_ws    = (const float*)d_in[10];
    const float* dec_bs    = (const float*)d_in[11];
    const float* dec_w_out = (const float*)d_in[12];
    const float* dec_b_out = (const float*)d_in[13];
    float* out = (float*)d_out;

    __half *h0, *l0, *h1, *l1, *qh, *ql, *wh, *wl;
    float *zT, *cnh;
    cudaGetSymbolAddress((void**)&h0, g_h0);
    cudaGetSymbolAddress((void**)&l0, g_l0);
    cudaGetSymbolAddress((void**)&h1, g_h1);
    cudaGetSymbolAddress((void**)&l1, g_l1);
    cudaGetSymbolAddress((void**)&zT, g_zT);
    cudaGetSymbolAddress((void**)&qh, g_qh);
    cudaGetSymbolAddress((void**)&ql, g_ql);
    cudaGetSymbolAddress((void**)&wh, g_whi);
    cudaGetSymbolAddress((void**)&wl, g_wlo);
    cudaGetSymbolAddress((void**)&cnh, g_cnh);

    const int GEMM_SMEM = 2 * 49152 + 1024;
    const int VQ_SMEM = 512 * 64 * 4 + 512 * 4;
    cudaFuncSetAttribute(conv_mma_kernel<64, 128>, cudaFuncAttributeMaxDynamicSharedMemorySize, GEMM_SMEM);
    cudaFuncSetAttribute(conv_mma_kernel<128, 64>, cudaFuncAttributeMaxDynamicSharedMemorySize, GEMM_SMEM);
    cudaFuncSetAttribute(vq_kernel, cudaFuncAttributeMaxDynamicSharedMemorySize, VQ_SMEM);

    const int WSLOT = 196608;

    repack_all_kernel<<<dim3(768, 9), 256>>>(enc_ws, enc_w_out, dec_w_in, dec_ws, dec_w_out, wh, wl);
    cb_prep_kernel<<<1, 512>>>(codebook, cnh);
    e1_kernel<<<dim3(256, 16), 256>>>(inputs, enc_w_in, enc_b_in, h0, l0);
    // encoder: full 3-phase (protects VQ argmin)
    conv_mma_kernel<64, 128><<<dim3(2, 128, 16), 256, GEMM_SMEM>>>(h0, l0, wh + 0 * WSLOT, wl + 0 * WSLOT,
        enc_bs + 0, h1, l1, nullptr, 256, 256, 16384, 8192, 1, 1, 3);
    conv_mma_kernel<64, 128><<<dim3(2, 64, 16), 256, GEMM_SMEM>>>(h1, l1, wh + 1 * WSLOT, wl + 1 * WSLOT,
        enc_bs + 256, h0, l0, nullptr, 256, 256, 8192, 4096, 1, 1, 3);
    conv_mma_kernel<64, 128><<<dim3(2, 32, 16), 256, GEMM_SMEM>>>(h0, l0, wh + 2 * WSLOT, wl + 2 * WSLOT,
        enc_bs + 512, h1, l1, nullptr, 256, 256, 4096, 2048, 1, 1, 3);
    conv_mma_kernel<128, 64><<<dim3(1, 16, 16), 256, GEMM_SMEM>>>(h1, l1, wh + 3 * WSLOT, wl + 3 * WSLOT,
        enc_b_out, nullptr, nullptr, zT, 256, 64, 2048, 2048, 0, 0, 3);
    vq_kernel<<<256, 128, VQ_SMEM>>>(zT, codebook, cnh, qh, ql);
    // decoder: small layers full, two big convT at nph=2, final at nph=1
    conv_mma_kernel<64, 128><<<dim3(2, 32, 16), 256, GEMM_SMEM>>>(qh, ql, wh + 4 * WSLOT, wl + 4 * WSLOT,
        dec_b_in, h0, l0, nullptr, 64, 256, 2048, 2048, 0, 1, 3);
    conv_mma_kernel<64, 128><<<dim3(4, 32, 16), 256, GEMM_SMEM>>>(h0, l0, wh + 5 * WSLOT, wl + 5 * WSLOT,
        dec_bs + 0, h1, l1, nullptr, 256, 256, 2048, 4096, 2, 1, 3);
    conv_mma_kernel<64, 128><<<dim3(4, 64, 16), 256, GEMM_SMEM>>>(h1, l1, wh + 6 * WSLOT, wl + 6 * WSLOT,
        dec_bs + 256, h0, l0, nullptr, 256, 256, 4096, 8192, 2, 1, 2);
    conv_mma_kernel<64, 128><<<dim3(4, 128, 16), 256, GEMM_SMEM>>>(h0, l0, wh + 7 * WSLOT, wl + 7 * WSLOT,
        dec_bs + 512, h1, l1, nullptr, 256, 256, 8192, 16384, 2, 1, 2);
    conv_mma_kernel<64, 128><<<dim3(4, 256, 16), 256, GEMM_SMEM>>>(h1, l1, wh + 8 * WSLOT, wl + 8 * WSLOT,
        dec_b_out, nullptr, nullptr, out, 256, 256, 16384, 32768, 3, 0, 1);
}

// round 17
// speedup vs baseline: 1.5083x; 1.1142x over previous
#include <cuda_runtime.h>
#include <cuda_fp16.h>

typedef unsigned long long u64;
typedef unsigned int u32;
#define DI __device__ __forceinline__

#define LO_SCALE 2048.f
#define LO_INV (1.f / 2048.f)

// ---------------- static scratch ----------------
__device__ __half g_h0[16*16384*256];
__device__ __half g_l0[16*16384*256];
__device__ __half g_h1[16*16384*256];
__device__ __half g_l1[16*16384*256];
__device__ float  g_zT[16*2048*64];
__device__ __half g_qh[16*2048*64];
__device__ __half g_ql[16*2048*64];
__device__ __half g_whi[9*196608];
__device__ __half g_wlo[9*196608];
__device__ float  g_cnh[512];

// ---------------- PTX helpers ----------------
DI u32 smem_u32(const void* p) {
    u32 a;
    asm("{ .reg .u64 t; cvta.to.shared.u64 t, %1; cvt.u32.u64 %0, t; }" : "=r"(a) : "l"(p));
    return a;
}
DI void cpa16(u32 dst, const void* src, int src_sz) {
    asm volatile("cp.async.cg.shared.global [%0], [%1], 16, %2;"
                 :: "r"(dst), "l"(src), "r"(src_sz) : "memory");
}
DI void cpa_commit() { asm volatile("cp.async.commit_group;" ::: "memory"); }
DI void cpa_wait1() { asm volatile("cp.async.wait_group 1;" ::: "memory"); }
DI void cpa_wait0() { asm volatile("cp.async.wait_group 0;" ::: "memory"); }
DI void ldsm4(u32* r, u32 addr) {
    asm volatile("ldmatrix.sync.aligned.m8n8.x4.shared.b16 {%0,%1,%2,%3}, [%4];"
                 : "=r"(r[0]), "=r"(r[1]), "=r"(r[2]), "=r"(r[3]) : "r"(addr));
}
DI void mma16816(float* c, const u32* a, u32 b0, u32 b1) {
    asm volatile(
        "mma.sync.aligned.m16n8k16.row.col.f32.f16.f16.f32 "
        "{%0,%1,%2,%3}, {%4,%5,%6,%7}, {%8,%9}, {%0,%1,%2,%3};"
        : "+f"(c[0]), "+f"(c[1]), "+f"(c[2]), "+f"(c[3])
        : "r"(a[0]), "r"(a[1]), "r"(a[2]), "r"(a[3]), "r"(b0), "r"(b1));
}
DI u32 swz(u32 o) { return o ^ ((o >> 3) & 0x70); }

// ---------------- single merged weight repack: all 9 slots ----------------
__global__ void repack_all_kernel(const float* __restrict__ enc_ws,
                                  const float* __restrict__ enc_w_out,
                                  const float* __restrict__ dec_w_in,
                                  const float* __restrict__ dec_ws,
                                  const float* __restrict__ dec_w_out,
                                  __half* __restrict__ wh, __half* __restrict__ wl) {
    const int WSLOT = 196608;
    int slot = blockIdx.y;
    const float* src;
    int OC, IC;
    if (slot < 3)       { src = enc_ws + slot * 196608;       OC = 256; IC = 256; }
    else if (slot == 3) { src = enc_w_out;                    OC = 64;  IC = 256; }
    else if (slot == 4) { src = dec_w_in;                     OC = 256; IC = 64;  }
    else if (slot < 8)  { src = dec_ws + (slot - 5) * 196608; OC = 256; IC = 256; }
    else                { src = dec_w_out;                    OC = 256; IC = 256; }

    int i = blockIdx.x * 256 + threadIdx.x;
    int n = OC * IC * 3;
    if (i >= n) return;
    int oc = i / (IC * 3);
    int r = i - oc * IC * 3;
    int ic = r / 3, k = r - ic * 3;
    int nch = IC >> 6, c = ic >> 6, j = ic & 63;
    float v = src[i];
    __half h = __float2half_rn(v);
    size_t d = (size_t)slot * WSLOT + ((size_t)(k * nch + c) * OC + oc) * 64 + j;
    wh[d] = h;
    wl[d] = __float2half_rn((v - __half2float(h)) * LO_SCALE);
}

__global__ void cb_prep_kernel(const float* __restrict__ cb, float* __restrict__ cnh) {
    int c = threadIdx.x;
    float s = 0.f;
    for (int k = 0; k < 64; k++) { float v = cb[c * 64 + k]; s += v * v; }
    cnh[c] = 0.5f * s;
}

// ---------------- encoder layer 1: IC=1, stride 2, relu, t-major hi/lo out ----------------
__global__ void e1_kernel(const float* __restrict__ x, const float* __restrict__ w,
                          const float* __restrict__ bias,
                          __half* __restrict__ oh, __half* __restrict__ ol) {
    __shared__ float xs[132];
    int b = blockIdx.y, tc = blockIdx.x * 64, tid = threadIdx.x;
    const float* xr = x + (size_t)b * 32768;
    for (int i = tid; i < 130; i += 256) {
        int pos = 2 * tc - 1 + i;
        xs[i] = (pos >= 0 && pos < 32768) ? xr[pos] : 0.f;
    }
    __syncthreads();
    float w0 = w[tid * 3], w1 = w[tid * 3 + 1], w2 = w[tid * 3 + 2], bv = bias[tid];
    for (int j = 0; j < 64; j++) {
        float v = fmaxf(bv + w0 * xs[2 * j] + w1 * xs[2 * j + 1] + w2 * xs[2 * j + 2], 0.f);
        __half h = __float2half_rn(v);
        size_t o = ((size_t)b * 16384 + tc + j) * 256 + tid;
        oh[o] = h;
        ol[o] = __float2half_rn((v - __half2float(h)) * LO_SCALE);
    }
}

// ---------------- generic mma.sync conv GEMM (fp16-split, scaled residuals) ----------------
// mode: 0=s1 conv, 1=s2 conv, 2=convT (pair-split), 3=convT final (fp32 ch-major out)
// nph:  3 = full split; 2 = phases 1+3 (drop weight residual); 1 = hi-only
// out_lo == nullptr -> skip residual store (consumer is hi-only)
// grid: x = oc-tile (+pair for mode>=2), y = t-tile (BM rows), z = batch
template <int BM, int BN>
__global__ void __launch_bounds__(256, 2)
conv_mma_kernel(const __half* __restrict__ in_hi, const __half* __restrict__ in_lo,
                const __half* __restrict__ w_hi, const __half* __restrict__ w_lo,
                const float* __restrict__ bias,
                __half* __restrict__ out_hi, __half* __restrict__ out_lo,
                float* __restrict__ out_f32,
                int IC, int OC, int Tin, int Tout, int mode, int relu, int nph) {
    const int WN = BN / 32;
    const int ASZ = BM * 128;
    const int BSZ = BN * 128;
    const int STAGE = 2 * (ASZ + BSZ);   // 48KB

    extern __shared__ char smraw[];
    u32 sb0 = smem_u32(smraw);
    u32 sb = (sb0 + 1023) & ~1023u;
    char* smp = smraw + (sb - sb0);

    const int tid = threadIdx.x, lane = tid & 31, wid = tid >> 5;
    const int t0 = blockIdx.y * BM;
    int xb = blockIdx.x;
    int oc0, pair;
    if (mode >= 2) { oc0 = (xb & 1) * 128; pair = xb >> 1; }
    else           { oc0 = xb * BN; pair = 0; }
    const int b = blockIdx.z;
    const int nch = IC >> 6;
    const int nsub = (mode < 2) ? 3 * nch : (pair ? 2 * nch : nch);
    const size_t inb = (size_t)b * Tin * IC;

    const int wm = wid / WN, wn = wid % WN;
    const int mbase = wm * 32;

    float acc[2][4][4];     // hi*hi
    float accc[2][4][4];    // cross terms (scaled by LO_SCALE)
#pragma unroll
    for (int mt = 0; mt < 2; mt++)
#pragma unroll
        for (int nt = 0; nt < 4; nt++)
#pragma unroll
            for (int k = 0; k < 4; k++) { acc[mt][nt][k] = 0.f; accc[mt][nt][k] = 0.f; }

    auto geo = [&](int i, int& c, int& kap, int& del) {
        if (mode < 2) { c = i / 3; int s = i - 3 * c; kap = s; del = s - 1; }
        else if (!pair) { c = i; kap = 1; del = 0; }
        else { c = i >> 1; if (i & 1) { kap = 2; del = 1; } else { kap = 0; del = 0; } }
    };
    // stage p: A_hi @0, A_lo @ASZ, B_hi @2*ASZ, B_lo @2*ASZ+BSZ
    auto load_chunk = [&](int i, int p) {
        int c, kap, del;
        geo(i, c, kap, del);
        u32 abase = sb + p * STAGE;
        u32 bbase = abase + 2 * ASZ;
        int r0 = tid >> 3, qd = tid & 7;
        const __half* sH = in_hi + inb + c * 64 + qd * 8;
        const __half* sL = in_lo + inb + c * 64 + qd * 8;
#pragma unroll
        for (int it = 0; it < BM / 32; it++) {
            int r = r0 + it * 32;
            int g = (mode == 1) ? (2 * (t0 + r) + del) : (t0 + r + del);
            int ok = (g >= 0 && g < Tin) ? 16 : 0;
            int gc = ok ? g : 0;
            u32 so = swz((u32)(r * 128 + qd * 16));
            cpa16(abase + so, sH + (size_t)gc * IC, ok);
            if (nph >= 2) cpa16(abase + ASZ + so, sL + (size_t)gc * IC, ok);
        }
        const __half* wH = w_hi + ((size_t)(kap * nch + c) * OC + oc0) * 64 + qd * 8;
        const __half* wL = w_lo + ((size_t)(kap * nch + c) * OC + oc0) * 64 + qd * 8;
#pragma unroll
        for (int it = 0; it < BN / 32; it++) {
            int r = r0 + it * 32;
            u32 so = swz((u32)(r * 128 + qd * 16));
            cpa16(bbase + so, wH + (size_t)r * 64, 16);
            if (nph == 3) cpa16(bbase + BSZ + so, wL + (size_t)r * 64, 16);
        }
    };

    load_chunk(0, 0);
    cpa_commit();
    if (nsub > 1) { load_chunk(1, 1); cpa_commit(); }

    for (int i = 0; i < nsub; i++) {
        int p = i & 1;
        if (i + 1 < nsub) cpa_wait1(); else cpa_wait0();
        __syncthreads();

        u32 abase = sb + p * STAGE;
        u32 bbase = abase + 2 * ASZ;
#pragma unroll
        for (int ks = 0; ks < 4; ks++) {
            int arow = mbase + (lane & 15);
            int akb = ks * 32 + (lane >> 4) * 16;
            u32 aad0 = abase + swz((u32)(arow * 128 + akb));
            u32 aad1 = abase + swz((u32)((arow + 16) * 128 + akb));

            u32 ah[2][4], bh[8];
            ldsm4(ah[0], aad0);
            ldsm4(ah[1], aad1);
            u32 badr[2];
#pragma unroll
            for (int q = 0; q < 2; q++) {
                int brow = wn * 32 + q * 16 + ((lane >> 4) & 1) * 8 + (lane & 7);
                int bkb = ks * 32 + ((lane >> 3) & 1) * 16;
                badr[q] = bbase + swz((u32)(brow * 128 + bkb));
                ldsm4(&bh[q * 4], badr[q]);
            }
            // Phase 1: hh -> acc
#pragma unroll
            for (int mt = 0; mt < 2; mt++)
#pragma unroll
                for (int nt = 0; nt < 4; nt++) {
                    int bi = (nt >> 1) * 4 + (nt & 1) * 2;
                    mma16816(acc[mt][nt], ah[mt], bh[bi], bh[bi + 1]);
                }
            if (nph == 3) {
                u32 bl[8];
                ldsm4(&bl[0], badr[0] + BSZ);
                ldsm4(&bl[4], badr[1] + BSZ);
                // Phase 2: A-hi x B-lo
#pragma unroll
                for (int mt = 0; mt < 2; mt++)
#pragma unroll
                    for (int nt = 0; nt < 4; nt++) {
                        int bi = (nt >> 1) * 4 + (nt & 1) * 2;
                        mma16816(accc[mt][nt], ah[mt], bl[bi], bl[bi + 1]);
                    }
            }
            if (nph >= 2) {
                u32 al[2][4];
                ldsm4(al[0], aad0 + ASZ);
                ldsm4(al[1], aad1 + ASZ);
                // Phase 3: A-lo x B-hi
#pragma unroll
                for (int mt = 0; mt < 2; mt++)
#pragma unroll
                    for (int nt = 0; nt < 4; nt++) {
                        int bi = (nt >> 1) * 4 + (nt & 1) * 2;
                        mma16816(accc[mt][nt], al[mt], bh[bi], bh[bi + 1]);
                    }
            }
        }
        __syncthreads();
        if (i + 2 < nsub) { load_chunk(i + 2, p); cpa_commit(); }
    }

    // ---------------- epilogue ----------------
    int g = lane >> 2, tg = lane & 3;
    float* stage = reinterpret_cast<float*>(smp);   // mode 3 staging [col][68]
    float corr = (nph >= 2) ? LO_INV : 0.f;
#pragma unroll
    for (int mt = 0; mt < 2; mt++) {
#pragma unroll
        for (int nt = 0; nt < 4; nt++) {
            int col = wn * 32 + nt * 8 + tg * 2;
            float bv0 = __ldg(bias + oc0 + col);
            float bv1 = __ldg(bias + oc0 + col + 1);
            int r0 = mbase + mt * 16 + g, r1 = r0 + 8;
            float v00 = acc[mt][nt][0] + accc[mt][nt][0] * corr + bv0;
            float v01 = acc[mt][nt][1] + accc[mt][nt][1] * corr + bv1;
            float v10 = acc[mt][nt][2] + accc[mt][nt][2] * corr + bv0;
            float v11 = acc[mt][nt][3] + accc[mt][nt][3] * corr + bv1;
            if (relu) {
                v00 = fmaxf(v00, 0.f); v01 = fmaxf(v01, 0.f);
                v10 = fmaxf(v10, 0.f); v11 = fmaxf(v11, 0.f);
            }
            if (mode == 3) {
                stage[col * 68 + r0] = v00; stage[(col + 1) * 68 + r0] = v01;
                stage[col * 68 + r1] = v10; stage[(col + 1) * 68 + r1] = v11;
            } else if (out_f32 != nullptr) {
                *reinterpret_cast<float2*>(out_f32 + ((size_t)b * Tout + t0 + r0) * OC + oc0 + col) =
                    make_float2(v00, v01);
                *reinterpret_cast<float2*>(out_f32 + ((size_t)b * Tout + t0 + r1) * OC + oc0 + col) =
                    make_float2(v10, v11);
            } else {
                int tr0 = (mode == 2) ? (2 * (t0 + r0) + pair) : (t0 + r0);
                int tr1 = (mode == 2) ? (2 * (t0 + r1) + pair) : (t0 + r1);
                size_t o0 = ((size_t)b * Tout + tr0) * OC + oc0 + col;
                size_t o1 = ((size_t)b * Tout + tr1) * OC + oc0 + col;
                __half h00 = __float2half_rn(v00), h01 = __float2half_rn(v01);
                __half h10 = __float2half_rn(v10), h11 = __float2half_rn(v11);
                *reinterpret_cast<__half2*>(out_hi + o0) = __halves2half2(h00, h01);
                *reinterpret_cast<__half2*>(out_hi + o1) = __halves2half2(h10, h11);
                if (out_lo != nullptr) {
                    *reinterpret_cast<__half2*>(out_lo + o0) =
                        __halves2half2(__float2half_rn((v00 - __half2float(h00)) * LO_SCALE),
                                       __float2half_rn((v01 - __half2float(h01)) * LO_SCALE));
                    *reinterpret_cast<__half2*>(out_lo + o1) =
                        __halves2half2(__float2half_rn((v10 - __half2float(h10)) * LO_SCALE),
                                       __float2half_rn((v11 - __half2float(h11)) * LO_SCALE));
                }
            }
        }
    }
    if (mode == 3) {
        __syncthreads();
        for (int q = 0; q < 32; q++) {
            int idx = q * 256 + tid;
            int r = idx >> 6, m = idx & 63;
            out_f32[((size_t)(b * 256 + oc0 + r)) * 32768 + 2 * (t0 + m) + pair] =
                stage[r * 68 + m];
        }
    }
}

// ---------------- VQ: exact fp32 nearest code, q -> hi/lo fp16 ----------------
__global__ void __launch_bounds__(128)
vq_kernel(const float* __restrict__ z, const float* __restrict__ cb,
          const float* __restrict__ cnh,
          __half* __restrict__ qh, __half* __restrict__ ql) {
    extern __shared__ float cbs[];
    int tid = threadIdx.x;
    for (int i = tid; i < 512 * 64 / 4; i += 128)
        reinterpret_cast<float4*>(cbs)[i] = reinterpret_cast<const float4*>(cb)[i];
    float* cns = cbs + 512 * 64;
    for (int i = tid; i < 512; i += 128) cns[i] = cnh[i];
    __syncthreads();

    int tg = blockIdx.x * 128 + tid;
    const float* zp = z + (size_t)tg * 64;
    float zr[64];
#pragma unroll
    for (int k = 0; k < 64; k++) zr[k] = zp[k];
    float best = -1e30f;
    int bi = 0;
    for (int c = 0; c < 512; c++) {
        const float* cr = cbs + c * 64;
        float dot = 0.f;
#pragma unroll
        for (int k = 0; k < 64; k++) dot = fmaf(zr[k], cr[k], dot);
        float s = dot - cns[c];
        if (s > best) { best = s; bi = c; }
    }
    const float* cw = cbs + bi * 64;
    __half2* oh = reinterpret_cast<__half2*>(qh + (size_t)tg * 64);
    __half2* ol = reinterpret_cast<__half2*>(ql + (size_t)tg * 64);
#pragma unroll
    for (int k = 0; k < 32; k++) {
        float a0 = cw[2 * k], a1 = cw[2 * k + 1];
        __half h0v = __float2half_rn(a0);
        __half h1v = __float2half_rn(a1);
        oh[k] = __halves2half2(h0v, h1v);
        ol[k] = __halves2half2(__float2half_rn((a0 - __half2float(h0v)) * LO_SCALE),
                               __float2half_rn((a1 - __half2float(h1v)) * LO_SCALE));
    }
}

// ---------------- launcher ----------------
extern "C" void kernel_launch(void* const* d_in, const int* in_sizes, int n_in,
                              void* d_out, int out_size) {
    (void)in_sizes; (void)n_in; (void)out_size;
    const float* inputs    = (const float*)d_in[0];
    const float* enc_w_in  = (const float*)d_in[1];
    const float* enc_b_in  = (const float*)d_in[2];
    const float* enc_ws    = (const float*)d_in[3];
    const float* enc_bs    = (const float*)d_in[4];
    const float* enc_w_out = (const float*)d_in[5];
    const float* enc_b_out = (const float*)d_in[6];
    const float* codebook  = (const float*)d_in[7];
    const float* dec_w_in  = (const float*)d_in[8];
    const float* dec_b_in  = (const float*)d_in[9];
    const float* dec_ws    = (const float*)d_in[10];
    const float* dec_bs    = (const float*)d_in[11];
    const float* dec_w_out = (const float*)d_in[12];
    const float* dec_b_out = (const float*)d_in[13];
    float* out = (float*)d_out;

    __half *h0, *l0, *h1, *l1, *qh, *ql, *wh, *wl;
    float *zT, *cnh;
    cudaGetSymbolAddress((void**)&h0, g_h0);
    cudaGetSymbolAddress((void**)&l0, g_l0);
    cudaGetSymbolAddress((void**)&h1, g_h1);
    cudaGetSymbolAddress((void**)&l1, g_l1);
    cudaGetSymbolAddress((void**)&zT, g_zT);
    cudaGetSymbolAddress((void**)&qh, g_qh);
    cudaGetSymbolAddress((void**)&ql, g_ql);
    cudaGetSymbolAddress((void**)&wh, g_whi);
    cudaGetSymbolAddress((void**)&wl, g_wlo);
    cudaGetSymbolAddress((void**)&cnh, g_cnh);

    const int GEMM_SMEM = 2 * 49152 + 1024;
    const int VQ_SMEM = 512 * 64 * 4 + 512 * 4;
    cudaFuncSetAttribute(conv_mma_kernel<64, 128>, cudaFuncAttributeMaxDynamicSharedMemorySize, GEMM_SMEM);
    cudaFuncSetAttribute(conv_mma_kernel<128, 64>, cudaFuncAttributeMaxDynamicSharedMemorySize, GEMM_SMEM);
    cudaFuncSetAttribute(vq_kernel, cudaFuncAttributeMaxDynamicSharedMemorySize, VQ_SMEM);

    const int WSLOT = 196608;

    repack_all_kernel<<<dim3(768, 9), 256>>>(enc_ws, enc_w_out, dec_w_in, dec_ws, dec_w_out, wh, wl);
    cb_prep_kernel<<<1, 512>>>(codebook, cnh);
    e1_kernel<<<dim3(256, 16), 256>>>(inputs, enc_w_in, enc_b_in, h0, l0);
    // encoder: full 3-phase (protects VQ argmin)
    conv_mma_kernel<64, 128><<<dim3(2, 128, 16), 256, GEMM_SMEM>>>(h0, l0, wh + 0 * WSLOT, wl + 0 * WSLOT,
        enc_bs + 0, h1, l1, nullptr, 256, 256, 16384, 8192, 1, 1, 3);
    conv_mma_kernel<64, 128><<<dim3(2, 64, 16), 256, GEMM_SMEM>>>(h1, l1, wh + 1 * WSLOT, wl + 1 * WSLOT,
        enc_bs + 256, h0, l0, nullptr, 256, 256, 8192, 4096, 1, 1, 3);
    conv_mma_kernel<64, 128><<<dim3(2, 32, 16), 256, GEMM_SMEM>>>(h0, l0, wh + 2 * WSLOT, wl + 2 * WSLOT,
        enc_bs + 512, h1, l1, nullptr, 256, 256, 4096, 2048, 1, 1, 3);
    conv_mma_kernel<128, 64><<<dim3(1, 16, 16), 256, GEMM_SMEM>>>(h1, l1, wh + 3 * WSLOT, wl + 3 * WSLOT,
        enc_b_out, nullptr, nullptr, zT, 256, 64, 2048, 2048, 0, 0, 3);
    vq_kernel<<<256, 128, VQ_SMEM>>>(zT, codebook, cnh, qh, ql);
    // decoder: dec_in full; convT1 nph=2 (no lo-store); convT2/convT3 hi-only (no lo-store); final hi-only
    conv_mma_kernel<64, 128><<<dim3(2, 32, 16), 256, GEMM_SMEM>>>(qh, ql, wh + 4 * WSLOT, wl + 4 * WSLOT,
        dec_b_in, h0, l0, nullptr, 64, 256, 2048, 2048, 0, 1, 3);
    conv_mma_kernel<64, 128><<<dim3(4, 32, 16), 256, GEMM_SMEM>>>(h0, l0, wh + 5 * WSLOT, wl + 5 * WSLOT,
        dec_bs + 0, h1, nullptr, nullptr, 256, 256, 2048, 4096, 2, 1, 2);
    conv_mma_kernel<64, 128><<<dim3(4, 64, 16), 256, GEMM_SMEM>>>(h1, nullptr, wh + 6 * WSLOT, wl + 6 * WSLOT,
        dec_bs + 256, h0, nullptr, nullptr, 256, 256, 4096, 8192, 2, 1, 1);
    conv_mma_kernel<64, 128><<<dim3(4, 128, 16), 256, GEMM_SMEM>>>(h0, nullptr, wh + 7 * WSLOT, wl + 7 * WSLOT,
        dec_bs + 512, h1, nullptr, nullptr, 256, 256, 8192, 16384, 2, 1, 1);
    conv_mma_kernel<64, 128><<<dim3(4, 256, 16), 256, GEMM_SMEM>>>(h1, nullptr, wh + 8 * WSLOT, wl + 8 * WSLOT,
        dec_b_out, nullptr, nullptr, out, 256, 256, 16384, 32768, 3, 0, 1);
}